// round 13
// baseline (speedup 1.0000x reference)
#include <cuda_runtime.h>
#include <cuda_fp16.h>
#include <cstdint>

#define TSEQ 2048
#define NB   4
#define NH   8
#define HIDD 1024
#define MROWS (NB*TSEQ)   // 8192

#define XF4 2097152
#define WF4 1310720

// ---------------- scratch (device globals; no allocations allowed) ----------
__device__ float g_P [MROWS*4096];
__device__ float g_Qc[MROWS*512];
__device__ float g_Kc[MROWS*512];
__device__ float g_Vc[MROWS*1024];
__device__ float g_Bt[MROWS*8];
__device__ float g_O [MROWS*1024];

__device__ __half g_Xh[MROWS*1024];
__device__ __half g_Oh[MROWS*1024];
#define WOFF_O 4194304
__device__ __half g_Wh[5242880];

// ---------------- PTX helpers (sm_80-class only; compute_103-safe) ----------
static __device__ __forceinline__ uint32_t smem_u32(const void* p) {
    uint32_t a;
    asm("{ .reg .u64 t; cvta.to.shared.u64 t, %1; cvt.u32.u64 %0, t; }"
        : "=r"(a) : "l"(p));
    return a;
}

#define LDSM4(r, a)                                                             \
    asm volatile("ldmatrix.sync.aligned.m8n8.x4.shared.b16 {%0,%1,%2,%3}, [%4];"\
        : "=r"((r)[0]), "=r"((r)[1]), "=r"((r)[2]), "=r"((r)[3]) : "r"(a))

#define MMA16816(d, a, b0, b1)                                                  \
    asm volatile(                                                               \
        "mma.sync.aligned.m16n8k16.row.col.f32.f16.f16.f32 "                    \
        "{%0,%1,%2,%3},{%4,%5,%6,%7},{%8,%9},{%0,%1,%2,%3};"                    \
        : "+f"((d)[0]), "+f"((d)[1]), "+f"((d)[2]), "+f"((d)[3])                \
        : "r"((a)[0]), "r"((a)[1]), "r"((a)[2]), "r"((a)[3]), "r"(b0), "r"(b1))

#define CPA16(dst, src)                                                         \
    asm volatile("cp.async.cg.shared.global [%0], [%1], 16;"                    \
        :: "r"(dst), "l"(src) : "memory")
#define CPA4(dst, src)                                                          \
    asm volatile("cp.async.ca.shared.global [%0], [%1], 4;"                     \
        :: "r"(dst), "l"(src) : "memory")

// ---------------- prep: x -> fp16 and all 6 weights -> fp16 (one launch) ----
__global__ __launch_bounds__(256) void prep_fp16(
    const float* __restrict__ x,
    const float* __restrict__ Wq, const float* __restrict__ Wk,
    const float* __restrict__ Wv, const float* __restrict__ Wa,
    const float* __restrict__ Wg, const float* __restrict__ Wo,
    __half* __restrict__ Xh, __half* __restrict__ Wh)
{
    const int i = blockIdx.x * 256 + threadIdx.x;
    if (i < XF4) {
        const float4 v = ((const float4*)x)[i];
        __half2 H0; H0.x = __float2half_rn(v.x); H0.y = __float2half_rn(v.y);
        __half2 H1; H1.x = __float2half_rn(v.z); H1.y = __float2half_rn(v.w);
        *(__half2*)(Xh + (size_t)i * 4)     = H0;
        *(__half2*)(Xh + (size_t)i * 4 + 2) = H1;
        return;
    }
    const int j = i - XF4;
    if (j >= WF4) return;
    const float* src; int base;
    if (j < 262144)      { if (j < 131072) { src = Wq; base = 0; }
                           else            { src = Wk; base = 131072; } }
    else if (j < 786432) { if (j < 524288) { src = Wv; base = 262144; }
                           else            { src = Wa; base = 524288; } }
    else                 { if (j < 1048576){ src = Wg; base = 786432; }
                           else            { src = Wo; base = 1048576; } }
    const float4 v = ((const float4*)src)[j - base];
    __half2 H0; H0.x = __float2half_rn(v.x); H0.y = __float2half_rn(v.y);
    __half2 H1; H1.x = __float2half_rn(v.z); H1.y = __float2half_rn(v.w);
    *(__half2*)(Wh + (size_t)j * 4)     = H0;
    *(__half2*)(Wh + (size_t)j * 4 + 2) = H1;
}

// ------- HMMA GEMM: C = A @ B^T, fp16 inputs, fp32 accum -------------------
#define STGB  20480u
#define GSMEM (3*20480)

__global__ __launch_bounds__(256, 2) void gemm_hmma(
    const __half* __restrict__ Ah, const __half* __restrict__ Bh,
    const float* __restrict__ bias, float* __restrict__ C, int Nt,
    int bias_lo, int bias_hi, int act_lo)
{
    extern __shared__ char smc[];
    const uint32_t sb = smem_u32(smc);
    const int tid = threadIdx.x;
    const int l   = tid & 31, wid = tid >> 5;
    const int wm  = wid & 1, wn = wid >> 1;
    const int m0  = blockIdx.y << 7, n0 = blockIdx.x << 7;
    const int grp = l >> 3;

    const bool act  = (n0 >= act_lo);
    const bool hasb = bias && (n0 >= bias_lo) && (n0 < bias_hi);

    const uint32_t a_off = (uint32_t)((wm*64 + (grp & 1)*8 + (l & 7)) * 80
                                      + (grp >> 1) * 16);
    const uint32_t b_off = (uint32_t)((wn*32 + (grp >> 1)*8 + (l & 7)) * 80
                                      + (grp & 1) * 16);

    const __half* s0 = Ah + (size_t)m0 * 1024;
    const __half* s1 = Bh + (size_t)n0 * 1024;

    float acc[4][4][4];
#pragma unroll
    for (int mt = 0; mt < 4; mt++)
#pragma unroll
        for (int nt = 0; nt < 4; nt++)
#pragma unroll
            for (int r = 0; r < 4; r++) acc[mt][nt][r] = 0.f;

#define LOAD_BUF(buf, k0) do {                                                  \
    const uint32_t bb_ = sb + (uint32_t)(buf) * STGB;                           \
    const __half* ss_[2] = { s0, s1 };                                          \
    _Pragma("unroll")                                                           \
    for (int t2 = 0; t2 < 2; t2++) {                                            \
        _Pragma("unroll")                                                       \
        for (int it = 0; it < 2; it++) {                                        \
            const int idx_ = it * 256 + tid;                                    \
            const int row_ = idx_ >> 2, ch_ = idx_ & 3;                         \
            const uint32_t dst_ = bb_ + t2 * 10240u + row_ * 80u + ch_ * 16u;   \
            const __half* src_ = ss_[t2] + (size_t)row_ * 1024 + (k0) + ch_ * 8;\
            CPA16(dst_, src_);                                                  \
        }                                                                       \
    }                                                                           \
    asm volatile("cp.async.commit_group;" ::: "memory");                        \
} while (0)

#define MMAPASS(af, bf) do {                                                    \
    _Pragma("unroll")                                                           \
    for (int mt = 0; mt < 4; mt++)                                              \
        _Pragma("unroll")                                                       \
        for (int nt = 0; nt < 4; nt++)                                          \
            MMA16816(acc[mt][nt], (af) + 4*mt,                                  \
                     (bf)[(nt >> 1)*4 + (nt & 1)*2],                            \
                     (bf)[(nt >> 1)*4 + (nt & 1)*2 + 1]);                       \
} while (0)

    LOAD_BUF(0, 0);
    LOAD_BUF(1, 32);

    for (int c = 0; c < 32; c++) {
        if (c + 1 < 32)
            asm volatile("cp.async.wait_group 1;" ::: "memory");
        else
            asm volatile("cp.async.wait_group 0;" ::: "memory");
        __syncthreads();
        const uint32_t bb = sb + (uint32_t)(c % 3) * STGB;

        uint32_t a0[16], a1[16], b0[8], b1[8];
#pragma unroll
        for (int np = 0; np < 2; np++)
            LDSM4(b0 + 4*np, bb + 10240u + b_off + np * 1280u);
#pragma unroll
        for (int mt = 0; mt < 4; mt++)
            LDSM4(a0 + 4*mt, bb + a_off + mt * 1280u);

        MMAPASS(a0, b0);

        if (c + 2 < 32) LOAD_BUF((c + 2) % 3, (c + 2) * 32);

#pragma unroll
        for (int np = 0; np < 2; np++)
            LDSM4(b1 + 4*np, bb + 10240u + b_off + np * 1280u + 32u);
#pragma unroll
        for (int mt = 0; mt < 4; mt++)
            LDSM4(a1 + 4*mt, bb + a_off + mt * 1280u + 32u);

        MMAPASS(a1, b1);
    }

    const int r0 = l >> 2, c0 = (l & 3) * 2;
#pragma unroll
    for (int mt = 0; mt < 4; mt++) {
        const int row = m0 + wm*64 + mt*16 + r0;
#pragma unroll
        for (int nt = 0; nt < 4; nt++) {
            const int col = n0 + wn*32 + nt*8 + c0;
            float b0v = 0.f, b1v = 0.f;
            if (hasb) { b0v = bias[col - bias_lo]; b1v = bias[col + 1 - bias_lo]; }
            float v00 = acc[mt][nt][0] + b0v;
            float v01 = acc[mt][nt][1] + b1v;
            float v10 = acc[mt][nt][2] + b0v;
            float v11 = acc[mt][nt][3] + b1v;
            if (act) {
                v00 = 1.f / (1.f + __expf(-v00));
                v01 = 1.f / (1.f + __expf(-v01));
                v10 = 1.f / (1.f + __expf(-v10));
                v11 = 1.f / (1.f + __expf(-v11));
            }
            float2 p0; p0.x = v00; p0.y = v01;
            float2 p1; p1.x = v10; p1.y = v11;
            *(float2*)(C + (size_t)row * Nt + col)       = p0;
            *(float2*)(C + (size_t)(row + 8) * Nt + col) = p1;
        }
    }
}

// ------ fused depthwise causal conv (K=4)+silu AND beta projection ----------
#define CONVBLK 16384

__global__ __launch_bounds__(256) void conv_beta(
    const float* __restrict__ P, const float* __restrict__ x,
    const float* __restrict__ qw, const float* __restrict__ qb,
    const float* __restrict__ kw, const float* __restrict__ kb2,
    const float* __restrict__ vw, const float* __restrict__ vb2,
    const float* __restrict__ Wb, const float* __restrict__ bb,
    float* __restrict__ Qc, float* __restrict__ Kc, float* __restrict__ Vc,
    float* __restrict__ Bt)
{
    if (blockIdx.x >= CONVBLK) {
        const int m = blockIdx.x - CONVBLK;
        const int w = threadIdx.x >> 5;
        const int lane = threadIdx.x & 31;
        const float* xr = x  + (size_t)m * HIDD;
        const float* wr = Wb + (size_t)w * HIDD;
        float s = 0.f;
#pragma unroll
        for (int k = lane * 4; k < HIDD; k += 128) {
            float4 xv = *(const float4*)(xr + k);
            float4 wv = *(const float4*)(wr + k);
            s += xv.x*wv.x + xv.y*wv.y + xv.z*wv.z + xv.w*wv.w;
        }
#pragma unroll
        for (int o = 16; o; o >>= 1) s += __shfl_xor_sync(0xffffffffu, s, o);
        if (lane == 0) Bt[m*8 + w] = 1.f / (1.f + __expf(-(s + bb[w])));
        return;
    }

    const int idx = blockIdx.x * 256 + threadIdx.x;
    const int ch = idx & 2047;
    const int g  = idx >> 11;
    const int m0 = g * 4;
    const int t0 = m0 & (TSEQ - 1);

    const float* wc; float bias0, scale; float* outp; int outC, oc;
    if (ch < 512)       { wc = qw + ch*4;        bias0 = qb[ch];        scale = 1.f;
                          outp = Qc; outC = 512;  oc = ch; }
    else if (ch < 1024) { const int c2 = ch-512; wc = kw + c2*4; bias0 = kb2[c2];
                          scale = 0.125f; outp = Kc; outC = 512; oc = c2; }
    else                { const int c2 = ch-1024; wc = vw + c2*4; bias0 = vb2[c2];
                          scale = 1.f; outp = Vc; outC = 1024; oc = c2; }

    const float* in = P + ch;
    float xv[7];
#pragma unroll
    for (int j = 0; j < 7; j++)
        xv[j] = (t0 - 3 + j >= 0) ? in[(size_t)(m0 - 3 + j) * 4096] : 0.f;

    const float w0 = wc[0], w1 = wc[1], w2 = wc[2], w3 = wc[3];
#pragma unroll
    for (int i = 0; i < 4; i++) {
        float a = bias0;
        a = fmaf(w0, xv[i],   a);
        a = fmaf(w1, xv[i+1], a);
        a = fmaf(w2, xv[i+2], a);
        a = fmaf(w3, xv[i+3], a);
        const float s = a * (1.f / (1.f + __expf(-a)));
        outp[(size_t)(m0 + i) * outC + oc] = s * scale;
    }
}

// ---------------- gated delta-rule recurrence (chunked cp.async) ------------
// grid (B*H, 8), block 64: 4 threads per v-column (16 columns/block).
// Thread q_ owns contiguous elements [16*q_, 16*q_+16) -> 4 float4 loads.
// Output reductions deferred to chunk end (off the serial critical path).
#define DCH 16

__global__ __launch_bounds__(64) void delta_recurrence(
    const float* __restrict__ Qc, const float* __restrict__ Kc,
    const float* __restrict__ Vc, const float* __restrict__ P,
    const float* __restrict__ Bt, float* __restrict__ O)
{
    const int bh = blockIdx.x;
    const int b = bh >> 3, h = bh & 7;
    const int tid = threadIdx.x;
    const int q_  = tid & 3;
    const int col = tid >> 2;                   // 0..15

    __shared__ __align__(16) float sk[2][DCH][72];
    __shared__ __align__(16) float sq[2][DCH][72];
    __shared__ __align__(16) float sv[2][DCH][16];
    __shared__ __align__(16) float sa[2][DCH][16];
    __shared__ __align__(16) float sbe[2][DCH];

    const uint32_t skb = smem_u32(sk);
    const uint32_t sqb = smem_u32(sq);
    const uint32_t svb = smem_u32(sv);
    const uint32_t sab = smem_u32(sa);
    const uint32_t sbb = smem_u32(sbe);

    float S[16];
#pragma unroll
    for (int i = 0; i < 16; i++) S[i] = 0.f;

    const float* kb  = Kc + (size_t)b * TSEQ * 512  + h * 64;
    const float* qb  = Qc + (size_t)b * TSEQ * 512  + h * 64;
    const float* vb  = Vc + (size_t)b * TSEQ * 1024 + h * 128 + blockIdx.y * 16;
    const float* ab  = P  + (size_t)b * TSEQ * 4096 + 2048 + h * 128 + blockIdx.y * 16;
    const float* bbp = Bt + (size_t)b * TSEQ * 8    + h;
    float*       ob  = O  + (size_t)b * TSEQ * 1024 + h * 128 + blockIdx.y * 16 + col;

#define DSTAGE(buf, t0) do {                                                    \
    _Pragma("unroll")                                                           \
    for (int i = 0; i < 4; i++) {                                               \
        const int idx = i * 64 + tid;                                           \
        const int row = idx >> 4, seg = idx & 15;                               \
        CPA16(skb + (uint32_t)(buf) * (DCH*72*4) + row * 288u + seg * 16u,      \
              kb + (size_t)((t0) + row) * 512 + seg * 4);                       \
        CPA16(sqb + (uint32_t)(buf) * (DCH*72*4) + row * 288u + seg * 16u,      \
              qb + (size_t)((t0) + row) * 512 + seg * 4);                       \
    }                                                                           \
    {                                                                           \
        const int row = tid >> 2, seg = tid & 3;                                \
        CPA16(svb + (uint32_t)(buf) * (DCH*16*4) + row * 64u + seg * 16u,       \
              vb + (size_t)((t0) + row) * 1024 + seg * 4);                      \
        CPA16(sab + (uint32_t)(buf) * (DCH*16*4) + row * 64u + seg * 16u,       \
              ab + (size_t)((t0) + row) * 4096 + seg * 4);                      \
    }                                                                           \
    if (tid < DCH)                                                              \
        CPA4(sbb + (uint32_t)(buf) * (DCH*4) + tid * 4u,                        \
             bbp + (size_t)((t0) + tid) * 8);                                   \
    asm volatile("cp.async.commit_group;" ::: "memory");                        \
} while (0)

    DSTAGE(0, 0);

    const int NCHUNK = TSEQ / DCH;
    for (int c = 0; c < NCHUNK; c++) {
        if (c + 1 < NCHUNK) {
            DSTAGE((c + 1) & 1, (c + 1) * DCH);
            asm volatile("cp.async.wait_group 1;" ::: "memory");
        } else {
            asm volatile("cp.async.wait_group 0;" ::: "memory");
        }
        __syncthreads();
        const int buf = c & 1;

        float op[DCH];
#pragma unroll 4
        for (int t = 0; t < DCH; t++) {
            const float4* k4 = (const float4*)&sk[buf][t][0];
            const float4* q4 = (const float4*)&sq[buf][t][0];
            const float be_c = sbe[buf][t];
            const float v_c  = sv[buf][t][col];
            const float a_c  = sa[buf][t][col];

            const float4 kA = k4[4*q_ + 0];
            const float4 kB = k4[4*q_ + 1];
            const float4 kC = k4[4*q_ + 2];
            const float4 kD = k4[4*q_ + 3];

            float d0, d1, d2, d3;
            d0 = kA.x * S[0];
            d1 = kA.y * S[1];
            d2 = kA.z * S[2];
            d3 = kA.w * S[3];
            d0 = fmaf(kB.x, S[4],  d0);
            d1 = fmaf(kB.y, S[5],  d1);
            d2 = fmaf(kB.z, S[6],  d2);
            d3 = fmaf(kB.w, S[7],  d3);
            d0 = fmaf(kC.x, S[8],  d0);
            d1 = fmaf(kC.y, S[9],  d1);
            d2 = fmaf(kC.z, S[10], d2);
            d3 = fmaf(kC.w, S[11], d3);
            d0 = fmaf(kD.x, S[12], d0);
            d1 = fmaf(kD.y, S[13], d1);
            d2 = fmaf(kD.z, S[14], d2);
            d3 = fmaf(kD.w, S[15], d3);
            float rd = (d0 + d1) + (d2 + d3);
            rd += __shfl_xor_sync(0xffffffffu, rd, 1);
            rd += __shfl_xor_sync(0xffffffffu, rd, 2);
            const float ncc = be_c * (v_c - rd);

            S[0]  = fmaf(a_c, S[0],  ncc * kA.x);
            S[1]  = fmaf(a_c, S[1],  ncc * kA.y);
            S[2]  = fmaf(a_c, S[2],  ncc * kA.z);
            S[3]  = fmaf(a_c, S[3],  ncc * kA.w);
            S[4]  = fmaf(a_c, S[4],  ncc * kB.x);
            S[5]  = fmaf(a_c, S[5],  ncc * kB.y);
            S[6]  = fmaf(a_c, S[6],  ncc * kB.z);
            S[7]  = fmaf(a_c, S[7],  ncc * kB.w);
            S[8]  = fmaf(a_c, S[8],  ncc * kC.x);
            S[9]  = fmaf(a_c, S[9],  ncc * kC.y);
            S[10] = fmaf(a_c, S[10], ncc * kC.z);
            S[11] = fmaf(a_c, S[11], ncc * kC.w);
            S[12] = fmaf(a_c, S[12], ncc * kD.x);
            S[13] = fmaf(a_c, S[13], ncc * kD.y);
            S[14] = fmaf(a_c, S[14], ncc * kD.z);
            S[15] = fmaf(a_c, S[15], ncc * kD.w);

            // per-thread output partial (reduction deferred to chunk end)
            const float4 qA = q4[4*q_ + 0];
            const float4 qB = q4[4*q_ + 1];
            const float4 qC = q4[4*q_ + 2];
            const float4 qD = q4[4*q_ + 3];
            float o0, o1, o2, o3;
            o0 = qA.x * S[0];
            o1 = qA.y * S[1];
            o2 = qA.z * S[2];
            o3 = qA.w * S[3];
            o0 = fmaf(qB.x, S[4],  o0);
            o1 = fmaf(qB.y, S[5],  o1);
            o2 = fmaf(qB.z, S[6],  o2);
            o3 = fmaf(qB.w, S[7],  o3);
            o0 = fmaf(qC.x, S[8],  o0);
            o1 = fmaf(qC.y, S[9],  o1);
            o2 = fmaf(qC.z, S[10], o2);
            o3 = fmaf(qC.w, S[11], o3);
            o0 = fmaf(qD.x, S[12], o0);
            o1 = fmaf(qD.y, S[13], o1);
            o2 = fmaf(qD.z, S[14], o2);
            o3 = fmaf(qD.w, S[15], o3);
            op[t] = (o0 + o1) + (o2 + o3);
        }

        // deferred output reductions: independent chains, fully pipelined
#pragma unroll
        for (int t = 0; t < DCH; t++) {
            float oo = op[t];
            oo += __shfl_xor_sync(0xffffffffu, oo, 1);
            oo += __shfl_xor_sync(0xffffffffu, oo, 2);
            if (q_ == 0) ob[(size_t)(c * DCH + t) * 1024] = oo;
        }
        __syncthreads();
    }
}

// -------- LayerNorm over DV + sigmoid-gate multiply + fp16 convert ----------
__global__ __launch_bounds__(256) void ln_gate_fp16(
    const float* __restrict__ O, const float* __restrict__ P,
    const float* __restrict__ lnw, const float* __restrict__ lnb,
    __half* __restrict__ hi)
{
    const int g = blockIdx.x * 8 + (threadIdx.x >> 5);
    const int lane = threadIdx.x & 31;
    const int m = g >> 3, h = g & 7;
    const float* row  = O + (size_t)m * 1024 + h * 128;
    const float* grow = P + (size_t)m * 4096 + 3072 + h * 128;

    float xs[4];
    float sum = 0.f;
#pragma unroll
    for (int i = 0; i < 4; i++) { xs[i] = row[lane + 32*i]; sum += xs[i]; }
#pragma unroll
    for (int o = 16; o; o >>= 1) sum += __shfl_xor_sync(0xffffffffu, sum, o);
    const float mu = sum * (1.f / 128.f);

    float vs = 0.f;
#pragma unroll
    for (int i = 0; i < 4; i++) { const float d = xs[i] - mu; vs = fmaf(d, d, vs); }
#pragma unroll
    for (int o = 16; o; o >>= 1) vs += __shfl_xor_sync(0xffffffffu, vs, o);
    const float rstd = rsqrtf(vs * (1.f / 128.f) + 1e-5f);

#pragma unroll
    for (int i = 0; i < 4; i++) {
        const int c = lane + 32*i;
        const float val = ((xs[i] - mu) * rstd * lnw[c] + lnb[c]) * grow[c];
        hi[(size_t)m * 1024 + h * 128 + c] = __float2half_rn(val);
    }
}

// ---------------- launch ----------------------------------------------------
extern "C" void kernel_launch(void* const* d_in, const int* in_sizes, int n_in,
                              void* d_out, int out_size)
{
    const float* x   = (const float*)d_in[0];
    const float* Wq  = (const float*)d_in[1];
    const float* Wk  = (const float*)d_in[2];
    const float* Wv  = (const float*)d_in[3];
    const float* Wa  = (const float*)d_in[4];
    const float* ba  = (const float*)d_in[5];
    const float* Wb  = (const float*)d_in[6];
    const float* bbv = (const float*)d_in[7];
    const float* Wg  = (const float*)d_in[8];
    const float* Wo  = (const float*)d_in[9];
    const float* qcw = (const float*)d_in[10];
    const float* qcb = (const float*)d_in[11];
    const float* kcw = (const float*)d_in[12];
    const float* kcb = (const float*)d_in[13];
    const float* vcw = (const float*)d_in[14];
    const float* vcb = (const float*)d_in[15];
    const float* lnw = (const float*)d_in[16];
    const float* lnb = (const float*)d_in[17];
    float* outp = (float*)d_out;

    float *P, *Qc, *Kc, *Vc, *Bt, *O;
    __half *Xh, *Oh, *Wh;
    cudaGetSymbolAddress((void**)&P,  g_P);
    cudaGetSymbolAddress((void**)&Qc, g_Qc);
    cudaGetSymbolAddress((void**)&Kc, g_Kc);
    cudaGetSymbolAddress((void**)&Vc, g_Vc);
    cudaGetSymbolAddress((void**)&Bt, g_Bt);
    cudaGetSymbolAddress((void**)&O,  g_O);
    cudaGetSymbolAddress((void**)&Xh, g_Xh);
    cudaGetSymbolAddress((void**)&Oh, g_Oh);
    cudaGetSymbolAddress((void**)&Wh, g_Wh);

    cudaFuncSetAttribute(gemm_hmma, cudaFuncAttributeMaxDynamicSharedMemorySize, GSMEM);

    // 0: prep (x + all weights -> fp16)
    prep_fp16<<<(XF4 + WF4 + 255)/256, 256>>>(
        x, Wq, Wk, Wv, Wa, Wg, Wo, Xh, Wh);

    // 1: ONE fused projection GEMM (Q|K|V|A|G), N=4096
    gemm_hmma<<<dim3(32, 64), 256, GSMEM>>>(
        Xh, Wh, ba, P, 4096,
        /*bias_lo=*/2048, /*bias_hi=*/3072, /*act_lo=*/2048);

    // 2: conv+silu (Q,K,V) fused with beta projection
    conv_beta<<<CONVBLK + MROWS, 256>>>(
        P, x, qcw, qcb, kcw, kcb, vcw, vcb, Wb, bbv, Qc, Kc, Vc, Bt);

    // 3: sequential gated delta-rule scan (4 thr/col, deferred output reduce)
    delta_recurrence<<<dim3(NB*NH, 8), 64>>>(Qc, Kc, Vc, P, Bt, O);

    // 4: LN + gate + fp16 convert; 5: output projection
    ln_gate_fp16<<<MROWS, 256>>>(O, P, lnw, lnb, Oh);
    gemm_hmma<<<dim3(8, 64), 256, GSMEM>>>(
        Oh, Wh + WOFF_O, nullptr, outp, 1024,
        /*bias_lo=*/0, /*bias_hi=*/0, /*act_lo=*/1 << 30);
}

// round 14
// speedup vs baseline: 1.0920x; 1.0920x over previous
#include <cuda_runtime.h>
#include <cuda_fp16.h>
#include <cstdint>

#define TSEQ 2048
#define NB   4
#define NH   8
#define HIDD 1024
#define MROWS (NB*TSEQ)   // 8192

#define XF4 2097152
#define WF4 1310720

// ---------------- scratch (device globals; no allocations allowed) ----------
__device__ float g_P [MROWS*4096];
__device__ float g_Qc[MROWS*512];
__device__ float g_Kc[MROWS*512];
__device__ float g_Vc[MROWS*1024];
__device__ float g_Bt[MROWS*8];
__device__ float g_O [MROWS*1024];

__device__ __half g_Xh[MROWS*1024];
__device__ __half g_Oh[MROWS*1024];
#define WOFF_O 4194304
__device__ __half g_Wh[5242880];

// ---------------- PTX helpers (sm_80-class only; compute_103-safe) ----------
static __device__ __forceinline__ uint32_t smem_u32(const void* p) {
    uint32_t a;
    asm("{ .reg .u64 t; cvta.to.shared.u64 t, %1; cvt.u32.u64 %0, t; }"
        : "=r"(a) : "l"(p));
    return a;
}

#define LDSM4(r, a)                                                             \
    asm volatile("ldmatrix.sync.aligned.m8n8.x4.shared.b16 {%0,%1,%2,%3}, [%4];"\
        : "=r"((r)[0]), "=r"((r)[1]), "=r"((r)[2]), "=r"((r)[3]) : "r"(a))

#define MMA16816(d, a, b0, b1)                                                  \
    asm volatile(                                                               \
        "mma.sync.aligned.m16n8k16.row.col.f32.f16.f16.f32 "                    \
        "{%0,%1,%2,%3},{%4,%5,%6,%7},{%8,%9},{%0,%1,%2,%3};"                    \
        : "+f"((d)[0]), "+f"((d)[1]), "+f"((d)[2]), "+f"((d)[3])                \
        : "r"((a)[0]), "r"((a)[1]), "r"((a)[2]), "r"((a)[3]), "r"(b0), "r"(b1))

#define CPA16(dst, src)                                                         \
    asm volatile("cp.async.cg.shared.global [%0], [%1], 16;"                    \
        :: "r"(dst), "l"(src) : "memory")
#define CPA4(dst, src)                                                          \
    asm volatile("cp.async.ca.shared.global [%0], [%1], 4;"                     \
        :: "r"(dst), "l"(src) : "memory")

// ---------------- prep: x -> fp16 and all 6 weights -> fp16 (one launch) ----
__global__ __launch_bounds__(256) void prep_fp16(
    const float* __restrict__ x,
    const float* __restrict__ Wq, const float* __restrict__ Wk,
    const float* __restrict__ Wv, const float* __restrict__ Wa,
    const float* __restrict__ Wg, const float* __restrict__ Wo,
    __half* __restrict__ Xh, __half* __restrict__ Wh)
{
    const int i = blockIdx.x * 256 + threadIdx.x;
    if (i < XF4) {
        const float4 v = ((const float4*)x)[i];
        __half2 H0; H0.x = __float2half_rn(v.x); H0.y = __float2half_rn(v.y);
        __half2 H1; H1.x = __float2half_rn(v.z); H1.y = __float2half_rn(v.w);
        *(__half2*)(Xh + (size_t)i * 4)     = H0;
        *(__half2*)(Xh + (size_t)i * 4 + 2) = H1;
        return;
    }
    const int j = i - XF4;
    if (j >= WF4) return;
    const float* src; int base;
    if (j < 262144)      { if (j < 131072) { src = Wq; base = 0; }
                           else            { src = Wk; base = 131072; } }
    else if (j < 786432) { if (j < 524288) { src = Wv; base = 262144; }
                           else            { src = Wa; base = 524288; } }
    else                 { if (j < 1048576){ src = Wg; base = 786432; }
                           else            { src = Wo; base = 1048576; } }
    const float4 v = ((const float4*)src)[j - base];
    __half2 H0; H0.x = __float2half_rn(v.x); H0.y = __float2half_rn(v.y);
    __half2 H1; H1.x = __float2half_rn(v.z); H1.y = __float2half_rn(v.w);
    *(__half2*)(Wh + (size_t)j * 4)     = H0;
    *(__half2*)(Wh + (size_t)j * 4 + 2) = H1;
}

// ------- HMMA GEMM: C = A @ B^T, fp16 inputs, fp32 accum -------------------
#define STGB  20480u
#define GSMEM (3*20480)

__global__ __launch_bounds__(256, 2) void gemm_hmma(
    const __half* __restrict__ Ah, const __half* __restrict__ Bh,
    const float* __restrict__ bias, float* __restrict__ C, int Nt,
    int bias_lo, int bias_hi, int act_lo)
{
    extern __shared__ char smc[];
    const uint32_t sb = smem_u32(smc);
    const int tid = threadIdx.x;
    const int l   = tid & 31, wid = tid >> 5;
    const int wm  = wid & 1, wn = wid >> 1;
    const int m0  = blockIdx.y << 7, n0 = blockIdx.x << 7;
    const int grp = l >> 3;

    const bool act  = (n0 >= act_lo);
    const bool hasb = bias && (n0 >= bias_lo) && (n0 < bias_hi);

    const uint32_t a_off = (uint32_t)((wm*64 + (grp & 1)*8 + (l & 7)) * 80
                                      + (grp >> 1) * 16);
    const uint32_t b_off = (uint32_t)((wn*32 + (grp >> 1)*8 + (l & 7)) * 80
                                      + (grp & 1) * 16);

    const __half* s0 = Ah + (size_t)m0 * 1024;
    const __half* s1 = Bh + (size_t)n0 * 1024;

    float acc[4][4][4];
#pragma unroll
    for (int mt = 0; mt < 4; mt++)
#pragma unroll
        for (int nt = 0; nt < 4; nt++)
#pragma unroll
            for (int r = 0; r < 4; r++) acc[mt][nt][r] = 0.f;

#define LOAD_BUF(buf, k0) do {                                                  \
    const uint32_t bb_ = sb + (uint32_t)(buf) * STGB;                           \
    const __half* ss_[2] = { s0, s1 };                                          \
    _Pragma("unroll")                                                           \
    for (int t2 = 0; t2 < 2; t2++) {                                            \
        _Pragma("unroll")                                                       \
        for (int it = 0; it < 2; it++) {                                        \
            const int idx_ = it * 256 + tid;                                    \
            const int row_ = idx_ >> 2, ch_ = idx_ & 3;                         \
            const uint32_t dst_ = bb_ + t2 * 10240u + row_ * 80u + ch_ * 16u;   \
            const __half* src_ = ss_[t2] + (size_t)row_ * 1024 + (k0) + ch_ * 8;\
            CPA16(dst_, src_);                                                  \
        }                                                                       \
    }                                                                           \
    asm volatile("cp.async.commit_group;" ::: "memory");                        \
} while (0)

#define MMAPASS(af, bf) do {                                                    \
    _Pragma("unroll")                                                           \
    for (int mt = 0; mt < 4; mt++)                                              \
        _Pragma("unroll")                                                       \
        for (int nt = 0; nt < 4; nt++)                                          \
            MMA16816(acc[mt][nt], (af) + 4*mt,                                  \
                     (bf)[(nt >> 1)*4 + (nt & 1)*2],                            \
                     (bf)[(nt >> 1)*4 + (nt & 1)*2 + 1]);                       \
} while (0)

    LOAD_BUF(0, 0);
    LOAD_BUF(1, 32);

    for (int c = 0; c < 32; c++) {
        if (c + 1 < 32)
            asm volatile("cp.async.wait_group 1;" ::: "memory");
        else
            asm volatile("cp.async.wait_group 0;" ::: "memory");
        __syncthreads();
        const uint32_t bb = sb + (uint32_t)(c % 3) * STGB;

        uint32_t a0[16], a1[16], b0[8], b1[8];
#pragma unroll
        for (int np = 0; np < 2; np++)
            LDSM4(b0 + 4*np, bb + 10240u + b_off + np * 1280u);
#pragma unroll
        for (int mt = 0; mt < 4; mt++)
            LDSM4(a0 + 4*mt, bb + a_off + mt * 1280u);

        MMAPASS(a0, b0);

        if (c + 2 < 32) LOAD_BUF((c + 2) % 3, (c + 2) * 32);

#pragma unroll
        for (int np = 0; np < 2; np++)
            LDSM4(b1 + 4*np, bb + 10240u + b_off + np * 1280u + 32u);
#pragma unroll
        for (int mt = 0; mt < 4; mt++)
            LDSM4(a1 + 4*mt, bb + a_off + mt * 1280u + 32u);

        MMAPASS(a1, b1);
    }

    const int r0 = l >> 2, c0 = (l & 3) * 2;
#pragma unroll
    for (int mt = 0; mt < 4; mt++) {
        const int row = m0 + wm*64 + mt*16 + r0;
#pragma unroll
        for (int nt = 0; nt < 4; nt++) {
            const int col = n0 + wn*32 + nt*8 + c0;
            float b0v = 0.f, b1v = 0.f;
            if (hasb) { b0v = bias[col - bias_lo]; b1v = bias[col + 1 - bias_lo]; }
            float v00 = acc[mt][nt][0] + b0v;
            float v01 = acc[mt][nt][1] + b1v;
            float v10 = acc[mt][nt][2] + b0v;
            float v11 = acc[mt][nt][3] + b1v;
            if (act) {
                v00 = 1.f / (1.f + __expf(-v00));
                v01 = 1.f / (1.f + __expf(-v01));
                v10 = 1.f / (1.f + __expf(-v10));
                v11 = 1.f / (1.f + __expf(-v11));
            }
            float2 p0; p0.x = v00; p0.y = v01;
            float2 p1; p1.x = v10; p1.y = v11;
            *(float2*)(C + (size_t)row * Nt + col)       = p0;
            *(float2*)(C + (size_t)(row + 8) * Nt + col) = p1;
        }
    }
}

// ------ fused depthwise causal conv (K=4)+silu AND beta projection ----------
#define CONVBLK 16384

__global__ __launch_bounds__(256) void conv_beta(
    const float* __restrict__ P, const float* __restrict__ x,
    const float* __restrict__ qw, const float* __restrict__ qb,
    const float* __restrict__ kw, const float* __restrict__ kb2,
    const float* __restrict__ vw, const float* __restrict__ vb2,
    const float* __restrict__ Wb, const float* __restrict__ bb,
    float* __restrict__ Qc, float* __restrict__ Kc, float* __restrict__ Vc,
    float* __restrict__ Bt)
{
    if (blockIdx.x >= CONVBLK) {
        const int m = blockIdx.x - CONVBLK;
        const int w = threadIdx.x >> 5;
        const int lane = threadIdx.x & 31;
        const float* xr = x  + (size_t)m * HIDD;
        const float* wr = Wb + (size_t)w * HIDD;
        float s = 0.f;
#pragma unroll
        for (int k = lane * 4; k < HIDD; k += 128) {
            float4 xv = *(const float4*)(xr + k);
            float4 wv = *(const float4*)(wr + k);
            s += xv.x*wv.x + xv.y*wv.y + xv.z*wv.z + xv.w*wv.w;
        }
#pragma unroll
        for (int o = 16; o; o >>= 1) s += __shfl_xor_sync(0xffffffffu, s, o);
        if (lane == 0) Bt[m*8 + w] = 1.f / (1.f + __expf(-(s + bb[w])));
        return;
    }

    const int idx = blockIdx.x * 256 + threadIdx.x;
    const int ch = idx & 2047;
    const int g  = idx >> 11;
    const int m0 = g * 4;
    const int t0 = m0 & (TSEQ - 1);

    const float* wc; float bias0, scale; float* outp; int outC, oc;
    if (ch < 512)       { wc = qw + ch*4;        bias0 = qb[ch];        scale = 1.f;
                          outp = Qc; outC = 512;  oc = ch; }
    else if (ch < 1024) { const int c2 = ch-512; wc = kw + c2*4; bias0 = kb2[c2];
                          scale = 0.125f; outp = Kc; outC = 512; oc = c2; }
    else                { const int c2 = ch-1024; wc = vw + c2*4; bias0 = vb2[c2];
                          scale = 1.f; outp = Vc; outC = 1024; oc = c2; }

    const float* in = P + ch;
    float xv[7];
#pragma unroll
    for (int j = 0; j < 7; j++)
        xv[j] = (t0 - 3 + j >= 0) ? in[(size_t)(m0 - 3 + j) * 4096] : 0.f;

    const float w0 = wc[0], w1 = wc[1], w2 = wc[2], w3 = wc[3];
#pragma unroll
    for (int i = 0; i < 4; i++) {
        float a = bias0;
        a = fmaf(w0, xv[i],   a);
        a = fmaf(w1, xv[i+1], a);
        a = fmaf(w2, xv[i+2], a);
        a = fmaf(w3, xv[i+3], a);
        const float s = a * (1.f / (1.f + __expf(-a)));
        outp[(size_t)(m0 + i) * outC + oc] = s * scale;
    }
}

// ---------------- gated delta-rule recurrence (chunked cp.async) ------------
// grid (B*H, 4), block 64: 4 threads per column; each thread carries TWO
// independent columns (col and col+16) of the same head, steps interleaved
// so one chain's FMA work hides the other's shuffle latency.
#define DCH 16

__global__ __launch_bounds__(64) void delta_recurrence(
    const float* __restrict__ Qc, const float* __restrict__ Kc,
    const float* __restrict__ Vc, const float* __restrict__ P,
    const float* __restrict__ Bt, float* __restrict__ O)
{
    const int bh = blockIdx.x;
    const int b = bh >> 3, h = bh & 7;
    const int tid = threadIdx.x;
    const int q_  = tid & 3;
    const int col = tid >> 2;                   // 0..15 (chain A); chain B = col+16

    __shared__ __align__(16) float sk[2][DCH][72];
    __shared__ __align__(16) float sq[2][DCH][72];
    __shared__ __align__(16) float sv[2][DCH][32];
    __shared__ __align__(16) float sa[2][DCH][32];
    __shared__ __align__(16) float sbe[2][DCH];

    const uint32_t skb = smem_u32(sk);
    const uint32_t sqb = smem_u32(sq);
    const uint32_t svb = smem_u32(sv);
    const uint32_t sab = smem_u32(sa);
    const uint32_t sbb = smem_u32(sbe);

    float SA[16], SB[16];
#pragma unroll
    for (int i = 0; i < 16; i++) { SA[i] = 0.f; SB[i] = 0.f; }

    const float* kb  = Kc + (size_t)b * TSEQ * 512  + h * 64;
    const float* qb  = Qc + (size_t)b * TSEQ * 512  + h * 64;
    const float* vb  = Vc + (size_t)b * TSEQ * 1024 + h * 128 + blockIdx.y * 32;
    const float* ab  = P  + (size_t)b * TSEQ * 4096 + 2048 + h * 128 + blockIdx.y * 32;
    const float* bbp = Bt + (size_t)b * TSEQ * 8    + h;
    float* obA = O + (size_t)b * TSEQ * 1024 + h * 128 + blockIdx.y * 32 + col;
    float* obB = obA + 16;

#define DSTAGE(buf, t0) do {                                                    \
    _Pragma("unroll")                                                           \
    for (int i = 0; i < 4; i++) {                                               \
        const int idx = i * 64 + tid;                                           \
        const int row = idx >> 4, seg = idx & 15;                               \
        CPA16(skb + (uint32_t)(buf) * (DCH*72*4) + row * 288u + seg * 16u,      \
              kb + (size_t)((t0) + row) * 512 + seg * 4);                       \
        CPA16(sqb + (uint32_t)(buf) * (DCH*72*4) + row * 288u + seg * 16u,      \
              qb + (size_t)((t0) + row) * 512 + seg * 4);                       \
    }                                                                           \
    _Pragma("unroll")                                                           \
    for (int i = 0; i < 2; i++) {                                               \
        const int idx = i * 64 + tid;                                           \
        const int row = idx >> 3, seg = idx & 7;                                \
        CPA16(svb + (uint32_t)(buf) * (DCH*32*4) + row * 128u + seg * 16u,      \
              vb + (size_t)((t0) + row) * 1024 + seg * 4);                      \
        CPA16(sab + (uint32_t)(buf) * (DCH*32*4) + row * 128u + seg * 16u,      \
              ab + (size_t)((t0) + row) * 4096 + seg * 4);                      \
    }                                                                           \
    if (tid < DCH)                                                              \
        CPA4(sbb + (uint32_t)(buf) * (DCH*4) + tid * 4u,                        \
             bbp + (size_t)((t0) + tid) * 8);                                   \
    asm volatile("cp.async.commit_group;" ::: "memory");                        \
} while (0)

    DSTAGE(0, 0);

    const int NCHUNK = TSEQ / DCH;
    for (int c = 0; c < NCHUNK; c++) {
        if (c + 1 < NCHUNK) {
            DSTAGE((c + 1) & 1, (c + 1) * DCH);
            asm volatile("cp.async.wait_group 1;" ::: "memory");
        } else {
            asm volatile("cp.async.wait_group 0;" ::: "memory");
        }
        __syncthreads();
        const int buf = c & 1;

#pragma unroll 4
        for (int t = 0; t < DCH; t++) {
            const float4* k4 = (const float4*)&sk[buf][t][0];
            const float4* q4 = (const float4*)&sq[buf][t][0];
            const float be_c = sbe[buf][t];
            const float vA = sv[buf][t][col],      aA = sa[buf][t][col];
            const float vB = sv[buf][t][col + 16], aB = sa[buf][t][col + 16];

            const float4 kA0 = k4[4*q_ + 0];
            const float4 kA1 = k4[4*q_ + 1];
            const float4 kA2 = k4[4*q_ + 2];
            const float4 kA3 = k4[4*q_ + 3];

            // --- interleaved dots (shared k) ---
            float dA0, dA1, dA2, dA3, dB0, dB1, dB2, dB3;
            dA0 = kA0.x * SA[0];  dB0 = kA0.x * SB[0];
            dA1 = kA0.y * SA[1];  dB1 = kA0.y * SB[1];
            dA2 = kA0.z * SA[2];  dB2 = kA0.z * SB[2];
            dA3 = kA0.w * SA[3];  dB3 = kA0.w * SB[3];
            dA0 = fmaf(kA1.x, SA[4],  dA0);  dB0 = fmaf(kA1.x, SB[4],  dB0);
            dA1 = fmaf(kA1.y, SA[5],  dA1);  dB1 = fmaf(kA1.y, SB[5],  dB1);
            dA2 = fmaf(kA1.z, SA[6],  dA2);  dB2 = fmaf(kA1.z, SB[6],  dB2);
            dA3 = fmaf(kA1.w, SA[7],  dA3);  dB3 = fmaf(kA1.w, SB[7],  dB3);
            dA0 = fmaf(kA2.x, SA[8],  dA0);  dB0 = fmaf(kA2.x, SB[8],  dB0);
            dA1 = fmaf(kA2.y, SA[9],  dA1);  dB1 = fmaf(kA2.y, SB[9],  dB1);
            dA2 = fmaf(kA2.z, SA[10], dA2);  dB2 = fmaf(kA2.z, SB[10], dB2);
            dA3 = fmaf(kA2.w, SA[11], dA3);  dB3 = fmaf(kA2.w, SB[11], dB3);
            dA0 = fmaf(kA3.x, SA[12], dA0);  dB0 = fmaf(kA3.x, SB[12], dB0);
            dA1 = fmaf(kA3.y, SA[13], dA1);  dB1 = fmaf(kA3.y, SB[13], dB1);
            dA2 = fmaf(kA3.z, SA[14], dA2);  dB2 = fmaf(kA3.z, SB[14], dB2);
            dA3 = fmaf(kA3.w, SA[15], dA3);  dB3 = fmaf(kA3.w, SB[15], dB3);
            float rdA = (dA0 + dA1) + (dA2 + dA3);
            float rdB = (dB0 + dB1) + (dB2 + dB3);
            rdA += __shfl_xor_sync(0xffffffffu, rdA, 1);
            rdB += __shfl_xor_sync(0xffffffffu, rdB, 1);
            rdA += __shfl_xor_sync(0xffffffffu, rdA, 2);
            rdB += __shfl_xor_sync(0xffffffffu, rdB, 2);
            const float nccA = be_c * (vA - rdA);
            const float nccB = be_c * (vB - rdB);

            const float4 qA0 = q4[4*q_ + 0];
            const float4 qA1 = q4[4*q_ + 1];
            const float4 qA2 = q4[4*q_ + 2];
            const float4 qA3 = q4[4*q_ + 3];

            float oA0, oA1, oA2, oA3, oB0, oB1, oB2, oB3;
            SA[0]  = fmaf(aA, SA[0],  nccA * kA0.x);  SB[0]  = fmaf(aB, SB[0],  nccB * kA0.x);
            SA[1]  = fmaf(aA, SA[1],  nccA * kA0.y);  SB[1]  = fmaf(aB, SB[1],  nccB * kA0.y);
            SA[2]  = fmaf(aA, SA[2],  nccA * kA0.z);  SB[2]  = fmaf(aB, SB[2],  nccB * kA0.z);
            SA[3]  = fmaf(aA, SA[3],  nccA * kA0.w);  SB[3]  = fmaf(aB, SB[3],  nccB * kA0.w);
            oA0 = qA0.x * SA[0];  oB0 = qA0.x * SB[0];
            oA1 = qA0.y * SA[1];  oB1 = qA0.y * SB[1];
            oA2 = qA0.z * SA[2];  oB2 = qA0.z * SB[2];
            oA3 = qA0.w * SA[3];  oB3 = qA0.w * SB[3];
            SA[4]  = fmaf(aA, SA[4],  nccA * kA1.x);  SB[4]  = fmaf(aB, SB[4],  nccB * kA1.x);
            SA[5]  = fmaf(aA, SA[5],  nccA * kA1.y);  SB[5]  = fmaf(aB, SB[5],  nccB * kA1.y);
            SA[6]  = fmaf(aA, SA[6],  nccA * kA1.z);  SB[6]  = fmaf(aB, SB[6],  nccB * kA1.z);
            SA[7]  = fmaf(aA, SA[7],  nccA * kA1.w);  SB[7]  = fmaf(aB, SB[7],  nccB * kA1.w);
            oA0 = fmaf(qA1.x, SA[4],  oA0);  oB0 = fmaf(qA1.x, SB[4],  oB0);
            oA1 = fmaf(qA1.y, SA[5],  oA1);  oB1 = fmaf(qA1.y, SB[5],  oB1);
            oA2 = fmaf(qA1.z, SA[6],  oA2);  oB2 = fmaf(qA1.z, SB[6],  oB2);
            oA3 = fmaf(qA1.w, SA[7],  oA3);  oB3 = fmaf(qA1.w, SB[7],  oB3);
            SA[8]  = fmaf(aA, SA[8],  nccA * kA2.x);  SB[8]  = fmaf(aB, SB[8],  nccB * kA2.x);
            SA[9]  = fmaf(aA, SA[9],  nccA * kA2.y);  SB[9]  = fmaf(aB, SB[9],  nccB * kA2.y);
            SA[10] = fmaf(aA, SA[10], nccA * kA2.z);  SB[10] = fmaf(aB, SB[10], nccB * kA2.z);
            SA[11] = fmaf(aA, SA[11], nccA * kA2.w);  SB[11] = fmaf(aB, SB[11], nccB * kA2.w);
            oA0 = fmaf(qA2.x, SA[8],  oA0);  oB0 = fmaf(qA2.x, SB[8],  oB0);
            oA1 = fmaf(qA2.y, SA[9],  oA1);  oB1 = fmaf(qA2.y, SB[9],  oB1);
            oA2 = fmaf(qA2.z, SA[10], oA2);  oB2 = fmaf(qA2.z, SB[10], oB2);
            oA3 = fmaf(qA2.w, SA[11], oA3);  oB3 = fmaf(qA2.w, SB[11], oB3);
            SA[12] = fmaf(aA, SA[12], nccA * kA3.x);  SB[12] = fmaf(aB, SB[12], nccB * kA3.x);
            SA[13] = fmaf(aA, SA[13], nccA * kA3.y);  SB[13] = fmaf(aB, SB[13], nccB * kA3.y);
            SA[14] = fmaf(aA, SA[14], nccA * kA3.z);  SB[14] = fmaf(aB, SB[14], nccB * kA3.z);
            SA[15] = fmaf(aA, SA[15], nccA * kA3.w);  SB[15] = fmaf(aB, SB[15], nccB * kA3.w);
            oA0 = fmaf(qA3.x, SA[12], oA0);  oB0 = fmaf(qA3.x, SB[12], oB0);
            oA1 = fmaf(qA3.y, SA[13], oA1);  oB1 = fmaf(qA3.y, SB[13], oB1);
            oA2 = fmaf(qA3.z, SA[14], oA2);  oB2 = fmaf(qA3.z, SB[14], oB2);
            oA3 = fmaf(qA3.w, SA[15], oA3);  oB3 = fmaf(qA3.w, SB[15], oB3);

            float ooA = (oA0 + oA1) + (oA2 + oA3);
            float ooB = (oB0 + oB1) + (oB2 + oB3);
            ooA += __shfl_xor_sync(0xffffffffu, ooA, 1);
            ooB += __shfl_xor_sync(0xffffffffu, ooB, 1);
            ooA += __shfl_xor_sync(0xffffffffu, ooA, 2);
            ooB += __shfl_xor_sync(0xffffffffu, ooB, 2);
            if (q_ == 0) {
                obA[(size_t)(c * DCH + t) * 1024] = ooA;
                obB[(size_t)(c * DCH + t) * 1024] = ooB;
            }
        }
        __syncthreads();
    }
}

// -------- LayerNorm over DV + sigmoid-gate multiply + fp16 convert ----------
__global__ __launch_bounds__(256) void ln_gate_fp16(
    const float* __restrict__ O, const float* __restrict__ P,
    const float* __restrict__ lnw, const float* __restrict__ lnb,
    __half* __restrict__ hi)
{
    const int g = blockIdx.x * 8 + (threadIdx.x >> 5);
    const int lane = threadIdx.x & 31;
    const int m = g >> 3, h = g & 7;
    const float* row  = O + (size_t)m * 1024 + h * 128;
    const float* grow = P + (size_t)m * 4096 + 3072 + h * 128;

    float xs[4];
    float sum = 0.f;
#pragma unroll
    for (int i = 0; i < 4; i++) { xs[i] = row[lane + 32*i]; sum += xs[i]; }
#pragma unroll
    for (int o = 16; o; o >>= 1) sum += __shfl_xor_sync(0xffffffffu, sum, o);
    const float mu = sum * (1.f / 128.f);

    float vs = 0.f;
#pragma unroll
    for (int i = 0; i < 4; i++) { const float d = xs[i] - mu; vs = fmaf(d, d, vs); }
#pragma unroll
    for (int o = 16; o; o >>= 1) vs += __shfl_xor_sync(0xffffffffu, vs, o);
    const float rstd = rsqrtf(vs * (1.f / 128.f) + 1e-5f);

#pragma unroll
    for (int i = 0; i < 4; i++) {
        const int c = lane + 32*i;
        const float val = ((xs[i] - mu) * rstd * lnw[c] + lnb[c]) * grow[c];
        hi[(size_t)m * 1024 + h * 128 + c] = __float2half_rn(val);
    }
}

// ---------------- launch ----------------------------------------------------
extern "C" void kernel_launch(void* const* d_in, const int* in_sizes, int n_in,
                              void* d_out, int out_size)
{
    const float* x   = (const float*)d_in[0];
    const float* Wq  = (const float*)d_in[1];
    const float* Wk  = (const float*)d_in[2];
    const float* Wv  = (const float*)d_in[3];
    const float* Wa  = (const float*)d_in[4];
    const float* ba  = (const float*)d_in[5];
    const float* Wb  = (const float*)d_in[6];
    const float* bbv = (const float*)d_in[7];
    const float* Wg  = (const float*)d_in[8];
    const float* Wo  = (const float*)d_in[9];
    const float* qcw = (const float*)d_in[10];
    const float* qcb = (const float*)d_in[11];
    const float* kcw = (const float*)d_in[12];
    const float* kcb = (const float*)d_in[13];
    const float* vcw = (const float*)d_in[14];
    const float* vcb = (const float*)d_in[15];
    const float* lnw = (const float*)d_in[16];
    const float* lnb = (const float*)d_in[17];
    float* outp = (float*)d_out;

    float *P, *Qc, *Kc, *Vc, *Bt, *O;
    __half *Xh, *Oh, *Wh;
    cudaGetSymbolAddress((void**)&P,  g_P);
    cudaGetSymbolAddress((void**)&Qc, g_Qc);
    cudaGetSymbolAddress((void**)&Kc, g_Kc);
    cudaGetSymbolAddress((void**)&Vc, g_Vc);
    cudaGetSymbolAddress((void**)&Bt, g_Bt);
    cudaGetSymbolAddress((void**)&O,  g_O);
    cudaGetSymbolAddress((void**)&Xh, g_Xh);
    cudaGetSymbolAddress((void**)&Oh, g_Oh);
    cudaGetSymbolAddress((void**)&Wh, g_Wh);

    cudaFuncSetAttribute(gemm_hmma, cudaFuncAttributeMaxDynamicSharedMemorySize, GSMEM);

    // 0: prep (x + all weights -> fp16)
    prep_fp16<<<(XF4 + WF4 + 255)/256, 256>>>(
        x, Wq, Wk, Wv, Wa, Wg, Wo, Xh, Wh);

    // 1: ONE fused projection GEMM (Q|K|V|A|G), N=4096
    gemm_hmma<<<dim3(32, 64), 256, GSMEM>>>(
        Xh, Wh, ba, P, 4096,
        /*bias_lo=*/2048, /*bias_hi=*/3072, /*act_lo=*/2048);

    // 2: conv+silu (Q,K,V) fused with beta projection
    conv_beta<<<CONVBLK + MROWS, 256>>>(
        P, x, qcw, qcb, kcw, kcb, vcw, vcb, Wb, bbv, Qc, Kc, Vc, Bt);

    // 3: sequential gated delta-rule scan (2 interleaved chains per thread)
    delta_recurrence<<<dim3(NB*NH, 4), 64>>>(Qc, Kc, Vc, P, Bt, O);

    // 4: LN + gate + fp16 convert; 5: output projection
    ln_gate_fp16<<<MROWS, 256>>>(O, P, lnw, lnb, Oh);
    gemm_hmma<<<dim3(8, 64), 256, GSMEM>>>(
        Oh, Wh + WOFF_O, nullptr, outp, 1024,
        /*bias_lo=*/0, /*bias_hi=*/0, /*act_lo=*/1 << 30);
}

// round 15
// speedup vs baseline: 1.2604x; 1.1542x over previous
#include <cuda_runtime.h>
#include <cuda_fp16.h>
#include <cstdint>

#define TSEQ 2048
#define NB   4
#define NH   8
#define HIDD 1024
#define MROWS (NB*TSEQ)   // 8192

#define XF4 2097152
#define WF4 1310720

// ---------------- scratch (device globals; no allocations allowed) ----------
__device__ float g_P [MROWS*4096];
__device__ float g_Qc[MROWS*512];
__device__ float g_Kc[MROWS*512];
__device__ float g_Vc[MROWS*1024];
__device__ float g_Bt[MROWS*8];
__device__ float g_O [MROWS*1024];

__device__ __half g_Xh[MROWS*1024];
__device__ __half g_Oh[MROWS*1024];
#define WOFF_O 4194304
__device__ __half g_Wh[5242880];

// ---------------- PTX helpers (sm_80-class only; compute_103-safe) ----------
static __device__ __forceinline__ uint32_t smem_u32(const void* p) {
    uint32_t a;
    asm("{ .reg .u64 t; cvta.to.shared.u64 t, %1; cvt.u32.u64 %0, t; }"
        : "=r"(a) : "l"(p));
    return a;
}

#define LDSM4(r, a)                                                             \
    asm volatile("ldmatrix.sync.aligned.m8n8.x4.shared.b16 {%0,%1,%2,%3}, [%4];"\
        : "=r"((r)[0]), "=r"((r)[1]), "=r"((r)[2]), "=r"((r)[3]) : "r"(a))

#define MMA16816(d, a, b0, b1)                                                  \
    asm volatile(                                                               \
        "mma.sync.aligned.m16n8k16.row.col.f32.f16.f16.f32 "                    \
        "{%0,%1,%2,%3},{%4,%5,%6,%7},{%8,%9},{%0,%1,%2,%3};"                    \
        : "+f"((d)[0]), "+f"((d)[1]), "+f"((d)[2]), "+f"((d)[3])                \
        : "r"((a)[0]), "r"((a)[1]), "r"((a)[2]), "r"((a)[3]), "r"(b0), "r"(b1))

#define CPA16(dst, src)                                                         \
    asm volatile("cp.async.cg.shared.global [%0], [%1], 16;"                    \
        :: "r"(dst), "l"(src) : "memory")
#define CPA4(dst, src)                                                          \
    asm volatile("cp.async.ca.shared.global [%0], [%1], 4;"                     \
        :: "r"(dst), "l"(src) : "memory")

// ---------------- prep: x -> fp16 and all 6 weights -> fp16 (one launch) ----
__global__ __launch_bounds__(256) void prep_fp16(
    const float* __restrict__ x,
    const float* __restrict__ Wq, const float* __restrict__ Wk,
    const float* __restrict__ Wv, const float* __restrict__ Wa,
    const float* __restrict__ Wg, const float* __restrict__ Wo,
    __half* __restrict__ Xh, __half* __restrict__ Wh)
{
    const int i = blockIdx.x * 256 + threadIdx.x;
    if (i < XF4) {
        const float4 v = ((const float4*)x)[i];
        __half2 H0; H0.x = __float2half_rn(v.x); H0.y = __float2half_rn(v.y);
        __half2 H1; H1.x = __float2half_rn(v.z); H1.y = __float2half_rn(v.w);
        *(__half2*)(Xh + (size_t)i * 4)     = H0;
        *(__half2*)(Xh + (size_t)i * 4 + 2) = H1;
        return;
    }
    const int j = i - XF4;
    if (j >= WF4) return;
    const float* src; int base;
    if (j < 262144)      { if (j < 131072) { src = Wq; base = 0; }
                           else            { src = Wk; base = 131072; } }
    else if (j < 786432) { if (j < 524288) { src = Wv; base = 262144; }
                           else            { src = Wa; base = 524288; } }
    else                 { if (j < 1048576){ src = Wg; base = 786432; }
                           else            { src = Wo; base = 1048576; } }
    const float4 v = ((const float4*)src)[j - base];
    __half2 H0; H0.x = __float2half_rn(v.x); H0.y = __float2half_rn(v.y);
    __half2 H1; H1.x = __float2half_rn(v.z); H1.y = __float2half_rn(v.w);
    *(__half2*)(Wh + (size_t)j * 4)     = H0;
    *(__half2*)(Wh + (size_t)j * 4 + 2) = H1;
}

// ------- HMMA GEMM: C = A @ B^T, fp16 inputs, fp32 accum -------------------
// 128x128 tile, BK=32, cp.async 3-stage pipeline; all 12 ldmatrix for both
// ks-groups issued back-to-back before the first MMA pass.
#define STGB  20480u
#define GSMEM (3*20480)

__global__ __launch_bounds__(256, 2) void gemm_hmma(
    const __half* __restrict__ Ah, const __half* __restrict__ Bh,
    const float* __restrict__ bias, float* __restrict__ C, int Nt,
    int bias_lo, int bias_hi, int act_lo)
{
    extern __shared__ char smc[];
    const uint32_t sb = smem_u32(smc);
    const int tid = threadIdx.x;
    const int l   = tid & 31, wid = tid >> 5;
    const int wm  = wid & 1, wn = wid >> 1;
    const int m0  = blockIdx.y << 7, n0 = blockIdx.x << 7;
    const int grp = l >> 3;

    const bool act  = (n0 >= act_lo);
    const bool hasb = bias && (n0 >= bias_lo) && (n0 < bias_hi);

    const uint32_t a_off = (uint32_t)((wm*64 + (grp & 1)*8 + (l & 7)) * 80
                                      + (grp >> 1) * 16);
    const uint32_t b_off = (uint32_t)((wn*32 + (grp >> 1)*8 + (l & 7)) * 80
                                      + (grp & 1) * 16);

    const __half* s0 = Ah + (size_t)m0 * 1024;
    const __half* s1 = Bh + (size_t)n0 * 1024;

    float acc[4][4][4];
#pragma unroll
    for (int mt = 0; mt < 4; mt++)
#pragma unroll
        for (int nt = 0; nt < 4; nt++)
#pragma unroll
            for (int r = 0; r < 4; r++) acc[mt][nt][r] = 0.f;

#define LOAD_BUF(buf, k0) do {                                                  \
    const uint32_t bb_ = sb + (uint32_t)(buf) * STGB;                           \
    const __half* ss_[2] = { s0, s1 };                                          \
    _Pragma("unroll")                                                           \
    for (int t2 = 0; t2 < 2; t2++) {                                            \
        _Pragma("unroll")                                                       \
        for (int it = 0; it < 2; it++) {                                        \
            const int idx_ = it * 256 + tid;                                    \
            const int row_ = idx_ >> 2, ch_ = idx_ & 3;                         \
            const uint32_t dst_ = bb_ + t2 * 10240u + row_ * 80u + ch_ * 16u;   \
            const __half* src_ = ss_[t2] + (size_t)row_ * 1024 + (k0) + ch_ * 8;\
            CPA16(dst_, src_);                                                  \
        }                                                                       \
    }                                                                           \
    asm volatile("cp.async.commit_group;" ::: "memory");                        \
} while (0)

#define MMAPASS(af, bf) do {                                                    \
    _Pragma("unroll")                                                           \
    for (int mt = 0; mt < 4; mt++)                                              \
        _Pragma("unroll")                                                       \
        for (int nt = 0; nt < 4; nt++)                                          \
            MMA16816(acc[mt][nt], (af) + 4*mt,                                  \
                     (bf)[(nt >> 1)*4 + (nt & 1)*2],                            \
                     (bf)[(nt >> 1)*4 + (nt & 1)*2 + 1]);                       \
} while (0)

    LOAD_BUF(0, 0);
    LOAD_BUF(1, 32);

    for (int c = 0; c < 32; c++) {
        if (c + 1 < 32)
            asm volatile("cp.async.wait_group 1;" ::: "memory");
        else
            asm volatile("cp.async.wait_group 0;" ::: "memory");
        __syncthreads();
        const uint32_t bb = sb + (uint32_t)(c % 3) * STGB;

        uint32_t a0[16], a1[16], b0[8], b1[8];
        // issue ALL fragment loads up front; first MMA's wait is covered by
        // the issue latency of the remaining ldmatrix ops
#pragma unroll
        for (int np = 0; np < 2; np++)
            LDSM4(b0 + 4*np, bb + 10240u + b_off + np * 1280u);
#pragma unroll
        for (int mt = 0; mt < 4; mt++)
            LDSM4(a0 + 4*mt, bb + a_off + mt * 1280u);
#pragma unroll
        for (int np = 0; np < 2; np++)
            LDSM4(b1 + 4*np, bb + 10240u + b_off + np * 1280u + 32u);
#pragma unroll
        for (int mt = 0; mt < 4; mt++)
            LDSM4(a1 + 4*mt, bb + a_off + mt * 1280u + 32u);

        MMAPASS(a0, b0);

        if (c + 2 < 32) LOAD_BUF((c + 2) % 3, (c + 2) * 32);

        MMAPASS(a1, b1);
    }

    const int r0 = l >> 2, c0 = (l & 3) * 2;
#pragma unroll
    for (int mt = 0; mt < 4; mt++) {
        const int row = m0 + wm*64 + mt*16 + r0;
#pragma unroll
        for (int nt = 0; nt < 4; nt++) {
            const int col = n0 + wn*32 + nt*8 + c0;
            float b0v = 0.f, b1v = 0.f;
            if (hasb) { b0v = bias[col - bias_lo]; b1v = bias[col + 1 - bias_lo]; }
            float v00 = acc[mt][nt][0] + b0v;
            float v01 = acc[mt][nt][1] + b1v;
            float v10 = acc[mt][nt][2] + b0v;
            float v11 = acc[mt][nt][3] + b1v;
            if (act) {
                v00 = 1.f / (1.f + __expf(-v00));
                v01 = 1.f / (1.f + __expf(-v01));
                v10 = 1.f / (1.f + __expf(-v10));
                v11 = 1.f / (1.f + __expf(-v11));
            }
            float2 p0; p0.x = v00; p0.y = v01;
            float2 p1; p1.x = v10; p1.y = v11;
            *(float2*)(C + (size_t)row * Nt + col)       = p0;
            *(float2*)(C + (size_t)(row + 8) * Nt + col) = p1;
        }
    }
}

// ------ fused depthwise causal conv (K=4)+silu AND beta projection ----------
// conv: 8 timesteps/thread. blocks [0, 8192): conv; [8192, 16384): beta.
#define CONVBLK 8192

__global__ __launch_bounds__(256) void conv_beta(
    const float* __restrict__ P, const float* __restrict__ x,
    const float* __restrict__ qw, const float* __restrict__ qb,
    const float* __restrict__ kw, const float* __restrict__ kb2,
    const float* __restrict__ vw, const float* __restrict__ vb2,
    const float* __restrict__ Wb, const float* __restrict__ bb,
    float* __restrict__ Qc, float* __restrict__ Kc, float* __restrict__ Vc,
    float* __restrict__ Bt)
{
    if (blockIdx.x >= CONVBLK) {
        const int m = blockIdx.x - CONVBLK;
        const int w = threadIdx.x >> 5;
        const int lane = threadIdx.x & 31;
        const float* xr = x  + (size_t)m * HIDD;
        const float* wr = Wb + (size_t)w * HIDD;
        float s = 0.f;
#pragma unroll
        for (int k = lane * 4; k < HIDD; k += 128) {
            float4 xv = *(const float4*)(xr + k);
            float4 wv = *(const float4*)(wr + k);
            s += xv.x*wv.x + xv.y*wv.y + xv.z*wv.z + xv.w*wv.w;
        }
#pragma unroll
        for (int o = 16; o; o >>= 1) s += __shfl_xor_sync(0xffffffffu, s, o);
        if (lane == 0) Bt[m*8 + w] = 1.f / (1.f + __expf(-(s + bb[w])));
        return;
    }

    const int idx = blockIdx.x * 256 + threadIdx.x;      // < (MROWS/8)*2048
    const int ch = idx & 2047;
    const int g  = idx >> 11;
    const int m0 = g * 8;
    const int t0 = m0 & (TSEQ - 1);

    const float* wc; float bias0, scale; float* outp; int outC, oc;
    if (ch < 512)       { wc = qw + ch*4;        bias0 = qb[ch];        scale = 1.f;
                          outp = Qc; outC = 512;  oc = ch; }
    else if (ch < 1024) { const int c2 = ch-512; wc = kw + c2*4; bias0 = kb2[c2];
                          scale = 0.125f; outp = Kc; outC = 512; oc = c2; }
    else                { const int c2 = ch-1024; wc = vw + c2*4; bias0 = vb2[c2];
                          scale = 1.f; outp = Vc; outC = 1024; oc = c2; }

    const float* in = P + ch;
    float xv[11];
#pragma unroll
    for (int j = 0; j < 11; j++)
        xv[j] = (t0 - 3 + j >= 0) ? in[(size_t)(m0 - 3 + j) * 4096] : 0.f;

    const float w0 = wc[0], w1 = wc[1], w2 = wc[2], w3 = wc[3];
#pragma unroll
    for (int i = 0; i < 8; i++) {
        float a = bias0;
        a = fmaf(w0, xv[i],   a);
        a = fmaf(w1, xv[i+1], a);
        a = fmaf(w2, xv[i+2], a);
        a = fmaf(w3, xv[i+3], a);
        const float s = a * (1.f / (1.f + __expf(-a)));
        outp[(size_t)(m0 + i) * outC + oc] = s * scale;
    }
}

// ---------------- gated delta-rule recurrence (R11, proven 245us) -----------
// grid (B*H, 8), block 64: 4 threads per v-column (16 columns/block).
#define DCH 16

__global__ __launch_bounds__(64) void delta_recurrence(
    const float* __restrict__ Qc, const float* __restrict__ Kc,
    const float* __restrict__ Vc, const float* __restrict__ P,
    const float* __restrict__ Bt, float* __restrict__ O)
{
    const int bh = blockIdx.x;
    const int b = bh >> 3, h = bh & 7;
    const int tid = threadIdx.x;
    const int q_  = tid & 3;
    const int col = tid >> 2;                   // 0..15

    __shared__ __align__(16) float sk[2][DCH][72];
    __shared__ __align__(16) float sq[2][DCH][72];
    __shared__ __align__(16) float sv[2][DCH][16];
    __shared__ __align__(16) float sa[2][DCH][16];
    __shared__ __align__(16) float sbe[2][DCH];

    const uint32_t skb = smem_u32(sk);
    const uint32_t sqb = smem_u32(sq);
    const uint32_t svb = smem_u32(sv);
    const uint32_t sab = smem_u32(sa);
    const uint32_t sbb = smem_u32(sbe);

    float S[16];
#pragma unroll
    for (int i = 0; i < 16; i++) S[i] = 0.f;

    const float* kb  = Kc + (size_t)b * TSEQ * 512  + h * 64;
    const float* qb  = Qc + (size_t)b * TSEQ * 512  + h * 64;
    const float* vb  = Vc + (size_t)b * TSEQ * 1024 + h * 128 + blockIdx.y * 16;
    const float* ab  = P  + (size_t)b * TSEQ * 4096 + 2048 + h * 128 + blockIdx.y * 16;
    const float* bbp = Bt + (size_t)b * TSEQ * 8    + h;
    float*       ob  = O  + (size_t)b * TSEQ * 1024 + h * 128 + blockIdx.y * 16 + col;

#define DSTAGE(buf, t0) do {                                                    \
    _Pragma("unroll")                                                           \
    for (int i = 0; i < 4; i++) {                                               \
        const int idx = i * 64 + tid;                                           \
        const int row = idx >> 4, seg = idx & 15;                               \
        CPA16(skb + (uint32_t)(buf) * (DCH*72*4) + row * 288u + seg * 16u,      \
              kb + (size_t)((t0) + row) * 512 + seg * 4);                       \
        CPA16(sqb + (uint32_t)(buf) * (DCH*72*4) + row * 288u + seg * 16u,      \
              qb + (size_t)((t0) + row) * 512 + seg * 4);                       \
    }                                                                           \
    {                                                                           \
        const int row = tid >> 2, seg = tid & 3;                                \
        CPA16(svb + (uint32_t)(buf) * (DCH*16*4) + row * 64u + seg * 16u,       \
              vb + (size_t)((t0) + row) * 1024 + seg * 4);                      \
        CPA16(sab + (uint32_t)(buf) * (DCH*16*4) + row * 64u + seg * 16u,       \
              ab + (size_t)((t0) + row) * 4096 + seg * 4);                      \
    }                                                                           \
    if (tid < DCH)                                                              \
        CPA4(sbb + (uint32_t)(buf) * (DCH*4) + tid * 4u,                        \
             bbp + (size_t)((t0) + tid) * 8);                                   \
    asm volatile("cp.async.commit_group;" ::: "memory");                        \
} while (0)

    DSTAGE(0, 0);

    const int NCHUNK = TSEQ / DCH;
    for (int c = 0; c < NCHUNK; c++) {
        if (c + 1 < NCHUNK) {
            DSTAGE((c + 1) & 1, (c + 1) * DCH);
            asm volatile("cp.async.wait_group 1;" ::: "memory");
        } else {
            asm volatile("cp.async.wait_group 0;" ::: "memory");
        }
        __syncthreads();
        const int buf = c & 1;

#pragma unroll 4
        for (int t = 0; t < DCH; t++) {
            const float2* k2 = (const float2*)&sk[buf][t][0];
            const float2* q2 = (const float2*)&sq[buf][t][0];
            const float be_c = sbe[buf][t];
            const float v_c  = sv[buf][t][col];
            const float a_c  = sa[buf][t][col];

            float kr[16];
#pragma unroll
            for (int jj = 0; jj < 8; jj++) {
                const float2 kv = k2[4*jj + q_];
                kr[2*jj]   = kv.x;
                kr[2*jj+1] = kv.y;
            }
            float d0 = 0.f, d1 = 0.f, d2 = 0.f, d3 = 0.f;
#pragma unroll
            for (int jj = 0; jj < 8; jj += 2) {
                d0 = fmaf(kr[2*jj],   S[2*jj],   d0);
                d1 = fmaf(kr[2*jj+1], S[2*jj+1], d1);
                d2 = fmaf(kr[2*jj+2], S[2*jj+2], d2);
                d3 = fmaf(kr[2*jj+3], S[2*jj+3], d3);
            }
            float rd = (d0 + d1) + (d2 + d3);
            rd += __shfl_xor_sync(0xffffffffu, rd, 1);
            rd += __shfl_xor_sync(0xffffffffu, rd, 2);
            const float ncc = be_c * (v_c - rd);

            float o0 = 0.f, o1 = 0.f;
#pragma unroll
            for (int jj = 0; jj < 8; jj++) {
                const float2 qv = q2[4*jj + q_];
                S[2*jj]   = fmaf(a_c, S[2*jj],   ncc * kr[2*jj]);
                S[2*jj+1] = fmaf(a_c, S[2*jj+1], ncc * kr[2*jj+1]);
                o0 = fmaf(qv.x, S[2*jj],   o0);
                o1 = fmaf(qv.y, S[2*jj+1], o1);
            }
            float oo = o0 + o1;
            oo += __shfl_xor_sync(0xffffffffu, oo, 1);
            oo += __shfl_xor_sync(0xffffffffu, oo, 2);
            if (q_ == 0) ob[(size_t)(c * DCH + t) * 1024] = oo;
        }
        __syncthreads();
    }
}

// -------- LayerNorm over DV + sigmoid-gate multiply + fp16 convert ----------
__global__ __launch_bounds__(256) void ln_gate_fp16(
    const float* __restrict__ O, const float* __restrict__ P,
    const float* __restrict__ lnw, const float* __restrict__ lnb,
    __half* __restrict__ hi)
{
    const int g = blockIdx.x * 8 + (threadIdx.x >> 5);
    const int lane = threadIdx.x & 31;
    const int m = g >> 3, h = g & 7;
    const float* row  = O + (size_t)m * 1024 + h * 128;
    const float* grow = P + (size_t)m * 4096 + 3072 + h * 128;

    float xs[4];
    float sum = 0.f;
#pragma unroll
    for (int i = 0; i < 4; i++) { xs[i] = row[lane + 32*i]; sum += xs[i]; }
#pragma unroll
    for (int o = 16; o; o >>= 1) sum += __shfl_xor_sync(0xffffffffu, sum, o);
    const float mu = sum * (1.f / 128.f);

    float vs = 0.f;
#pragma unroll
    for (int i = 0; i < 4; i++) { const float d = xs[i] - mu; vs = fmaf(d, d, vs); }
#pragma unroll
    for (int o = 16; o; o >>= 1) vs += __shfl_xor_sync(0xffffffffu, vs, o);
    const float rstd = rsqrtf(vs * (1.f / 128.f) + 1e-5f);

#pragma unroll
    for (int i = 0; i < 4; i++) {
        const int c = lane + 32*i;
        const float val = ((xs[i] - mu) * rstd * lnw[c] + lnb[c]) * grow[c];
        hi[(size_t)m * 1024 + h * 128 + c] = __float2half_rn(val);
    }
}

// ---------------- launch ----------------------------------------------------
extern "C" void kernel_launch(void* const* d_in, const int* in_sizes, int n_in,
                              void* d_out, int out_size)
{
    const float* x   = (const float*)d_in[0];
    const float* Wq  = (const float*)d_in[1];
    const float* Wk  = (const float*)d_in[2];
    const float* Wv  = (const float*)d_in[3];
    const float* Wa  = (const float*)d_in[4];
    const float* ba  = (const float*)d_in[5];
    const float* Wb  = (const float*)d_in[6];
    const float* bbv = (const float*)d_in[7];
    const float* Wg  = (const float*)d_in[8];
    const float* Wo  = (const float*)d_in[9];
    const float* qcw = (const float*)d_in[10];
    const float* qcb = (const float*)d_in[11];
    const float* kcw = (const float*)d_in[12];
    const float* kcb = (const float*)d_in[13];
    const float* vcw = (const float*)d_in[14];
    const float* vcb = (const float*)d_in[15];
    const float* lnw = (const float*)d_in[16];
    const float* lnb = (const float*)d_in[17];
    float* outp = (float*)d_out;

    float *P, *Qc, *Kc, *Vc, *Bt, *O;
    __half *Xh, *Oh, *Wh;
    cudaGetSymbolAddress((void**)&P,  g_P);
    cudaGetSymbolAddress((void**)&Qc, g_Qc);
    cudaGetSymbolAddress((void**)&Kc, g_Kc);
    cudaGetSymbolAddress((void**)&Vc, g_Vc);
    cudaGetSymbolAddress((void**)&Bt, g_Bt);
    cudaGetSymbolAddress((void**)&O,  g_O);
    cudaGetSymbolAddress((void**)&Xh, g_Xh);
    cudaGetSymbolAddress((void**)&Oh, g_Oh);
    cudaGetSymbolAddress((void**)&Wh, g_Wh);

    cudaFuncSetAttribute(gemm_hmma, cudaFuncAttributeMaxDynamicSharedMemorySize, GSMEM);

    // 0: prep (x + all weights -> fp16)
    prep_fp16<<<(XF4 + WF4 + 255)/256, 256>>>(
        x, Wq, Wk, Wv, Wa, Wg, Wo, Xh, Wh);

    // 1: ONE fused projection GEMM (Q|K|V|A|G), N=4096
    gemm_hmma<<<dim3(32, 64), 256, GSMEM>>>(
        Xh, Wh, ba, P, 4096,
        /*bias_lo=*/2048, /*bias_hi=*/3072, /*act_lo=*/2048);

    // 2: conv+silu (8 rows/thread) fused with beta projection
    conv_beta<<<CONVBLK + MROWS, 256>>>(
        P, x, qcw, qcb, kcw, kcb, vcw, vcb, Wb, bbv, Qc, Kc, Vc, Bt);

    // 3: sequential gated delta-rule scan (R11 proven config)
    delta_recurrence<<<dim3(NB*NH, 8), 64>>>(Qc, Kc, Vc, P, Bt, O);

    // 4: LN + gate + fp16 convert; 5: output projection
    ln_gate_fp16<<<MROWS, 256>>>(O, P, lnw, lnb, Oh);
    gemm_hmma<<<dim3(8, 64), 256, GSMEM>>>(
        Oh, Wh + WOFF_O, nullptr, outp, 1024,
        /*bias_lo=*/0, /*bias_hi=*/0, /*act_lo=*/1 << 30);
}

// round 16
// speedup vs baseline: 1.3413x; 1.0642x over previous
#include <cuda_runtime.h>
#include <cuda_fp16.h>
#include <cstdint>

#define TSEQ 2048
#define NB   4
#define NH   8
#define HIDD 1024
#define MROWS (NB*TSEQ)   // 8192

#define XF4 2097152
#define WF4 1310720

// ---------------- scratch (device globals; no allocations allowed) ----------
__device__ float g_P [MROWS*4096];
__device__ float g_Qc[MROWS*512];
__device__ float g_Kc[MROWS*512];
__device__ float g_Vc[MROWS*1024];
__device__ float g_Bt[MROWS*8];
__device__ float g_O [MROWS*1024];

__device__ __half g_Xh[MROWS*1024];
__device__ __half g_Oh[MROWS*1024];
#define WOFF_O 4194304
__device__ __half g_Wh[5242880];

// ---------------- PTX helpers (sm_80-class only; compute_103-safe) ----------
static __device__ __forceinline__ uint32_t smem_u32(const void* p) {
    uint32_t a;
    asm("{ .reg .u64 t; cvta.to.shared.u64 t, %1; cvt.u32.u64 %0, t; }"
        : "=r"(a) : "l"(p));
    return a;
}

#define LDSM4(r, a)                                                             \
    asm volatile("ldmatrix.sync.aligned.m8n8.x4.shared.b16 {%0,%1,%2,%3}, [%4];"\
        : "=r"((r)[0]), "=r"((r)[1]), "=r"((r)[2]), "=r"((r)[3]) : "r"(a))

#define MMA16816(d, a, b0, b1)                                                  \
    asm volatile(                                                               \
        "mma.sync.aligned.m16n8k16.row.col.f32.f16.f16.f32 "                    \
        "{%0,%1,%2,%3},{%4,%5,%6,%7},{%8,%9},{%0,%1,%2,%3};"                    \
        : "+f"((d)[0]), "+f"((d)[1]), "+f"((d)[2]), "+f"((d)[3])                \
        : "r"((a)[0]), "r"((a)[1]), "r"((a)[2]), "r"((a)[3]), "r"(b0), "r"(b1))

#define CPA16(dst, src)                                                         \
    asm volatile("cp.async.cg.shared.global [%0], [%1], 16;"                    \
        :: "r"(dst), "l"(src) : "memory")
#define CPA4(dst, src)                                                          \
    asm volatile("cp.async.ca.shared.global [%0], [%1], 4;"                     \
        :: "r"(dst), "l"(src) : "memory")

// ---------------- prep: x -> fp16 and all 6 weights -> fp16 (one launch) ----
__global__ __launch_bounds__(256) void prep_fp16(
    const float* __restrict__ x,
    const float* __restrict__ Wq, const float* __restrict__ Wk,
    const float* __restrict__ Wv, const float* __restrict__ Wa,
    const float* __restrict__ Wg, const float* __restrict__ Wo,
    __half* __restrict__ Xh, __half* __restrict__ Wh)
{
    const int i = blockIdx.x * 256 + threadIdx.x;
    if (i < XF4) {
        const float4 v = ((const float4*)x)[i];
        __half2 H0; H0.x = __float2half_rn(v.x); H0.y = __float2half_rn(v.y);
        __half2 H1; H1.x = __float2half_rn(v.z); H1.y = __float2half_rn(v.w);
        *(__half2*)(Xh + (size_t)i * 4)     = H0;
        *(__half2*)(Xh + (size_t)i * 4 + 2) = H1;
        return;
    }
    const int j = i - XF4;
    if (j >= WF4) return;
    const float* src; int base;
    if (j < 262144)      { if (j < 131072) { src = Wq; base = 0; }
                           else            { src = Wk; base = 131072; } }
    else if (j < 786432) { if (j < 524288) { src = Wv; base = 262144; }
                           else            { src = Wa; base = 524288; } }
    else                 { if (j < 1048576){ src = Wg; base = 786432; }
                           else            { src = Wo; base = 1048576; } }
    const float4 v = ((const float4*)src)[j - base];
    __half2 H0; H0.x = __float2half_rn(v.x); H0.y = __float2half_rn(v.y);
    __half2 H1; H1.x = __float2half_rn(v.z); H1.y = __float2half_rn(v.w);
    *(__half2*)(Wh + (size_t)j * 4)     = H0;
    *(__half2*)(Wh + (size_t)j * 4 + 2) = H1;
}

// ------- HMMA GEMM: C = A @ B^T, fp16 inputs, fp32 accum -------------------
// 128x128 tile, BK=64, cp.async 2-stage double buffer (73.7KB -> 2 CTA/SM).
// Pitch 144B (128B data + 16B pad): conflict-free per 8-lane phase.
#define STGB  36864u
#define GSMEM (2*36864)

__global__ __launch_bounds__(256, 2) void gemm_hmma(
    const __half* __restrict__ Ah, const __half* __restrict__ Bh,
    const float* __restrict__ bias, float* __restrict__ C, int Nt,
    int bias_lo, int bias_hi, int act_lo)
{
    extern __shared__ char smc[];
    const uint32_t sb = smem_u32(smc);
    const int tid = threadIdx.x;
    const int l   = tid & 31, wid = tid >> 5;
    const int wm  = wid & 1, wn = wid >> 1;
    const int m0  = blockIdx.y << 7, n0 = blockIdx.x << 7;
    const int grp = l >> 3;

    const bool act  = (n0 >= act_lo);
    const bool hasb = bias && (n0 >= bias_lo) && (n0 < bias_hi);

    const uint32_t a_off = (uint32_t)((wm*64 + (grp & 1)*8 + (l & 7)) * 144
                                      + (grp >> 1) * 16);
    const uint32_t b_off = (uint32_t)((wn*32 + (grp >> 1)*8 + (l & 7)) * 144
                                      + (grp & 1) * 16);

    const __half* s0 = Ah + (size_t)m0 * 1024;
    const __half* s1 = Bh + (size_t)n0 * 1024;

    float acc[4][4][4];
#pragma unroll
    for (int mt = 0; mt < 4; mt++)
#pragma unroll
        for (int nt = 0; nt < 4; nt++)
#pragma unroll
            for (int r = 0; r < 4; r++) acc[mt][nt][r] = 0.f;

#define LOAD_BUF(buf, k0) do {                                                  \
    const uint32_t bb_ = sb + (uint32_t)(buf) * STGB;                           \
    const __half* ss_[2] = { s0, s1 };                                          \
    _Pragma("unroll")                                                           \
    for (int t2 = 0; t2 < 2; t2++) {                                            \
        _Pragma("unroll")                                                       \
        for (int it = 0; it < 4; it++) {                                        \
            const int idx_ = it * 256 + tid;                                    \
            const int row_ = idx_ >> 3, ch_ = idx_ & 7;                         \
            const uint32_t dst_ = bb_ + t2 * 18432u + row_ * 144u + ch_ * 16u;  \
            const __half* src_ = ss_[t2] + (size_t)row_ * 1024 + (k0) + ch_ * 8;\
            CPA16(dst_, src_);                                                  \
        }                                                                       \
    }                                                                           \
    asm volatile("cp.async.commit_group;" ::: "memory");                        \
} while (0)

#define MMAPASS(af, bf) do {                                                    \
    _Pragma("unroll")                                                           \
    for (int mt = 0; mt < 4; mt++)                                              \
        _Pragma("unroll")                                                       \
        for (int nt = 0; nt < 4; nt++)                                          \
            MMA16816(acc[mt][nt], (af) + 4*mt,                                  \
                     (bf)[(nt >> 1)*4 + (nt & 1)*2],                            \
                     (bf)[(nt >> 1)*4 + (nt & 1)*2 + 1]);                       \
} while (0)

#define LDSM_SET(av, bv, ko) do {                                               \
    _Pragma("unroll")                                                           \
    for (int np = 0; np < 2; np++)                                              \
        LDSM4((bv) + 4*np, bb + 18432u + b_off + np * 2304u + (ko));            \
    _Pragma("unroll")                                                           \
    for (int mt = 0; mt < 4; mt++)                                              \
        LDSM4((av) + 4*mt, bb + a_off + mt * 2304u + (ko));                     \
} while (0)

    LOAD_BUF(0, 0);

    for (int c = 0; c < 16; c++) {
        asm volatile("cp.async.wait_group 0;" ::: "memory");
        __syncthreads();
        const uint32_t bb = sb + (uint32_t)(c & 1) * STGB;

        uint32_t a0[16], a1[16], b0[8], b1[8];
        LDSM_SET(a0, b0, 0u);
        MMAPASS(a0, b0);                        // ks0

        if (c + 1 < 16) LOAD_BUF((c + 1) & 1, (c + 1) * 64);

        LDSM_SET(a1, b1, 32u);
        MMAPASS(a1, b1);                        // ks1
        LDSM_SET(a0, b0, 64u);
        MMAPASS(a0, b0);                        // ks2
        LDSM_SET(a1, b1, 96u);
        MMAPASS(a1, b1);                        // ks3
    }

    const int r0 = l >> 2, c0 = (l & 3) * 2;
#pragma unroll
    for (int mt = 0; mt < 4; mt++) {
        const int row = m0 + wm*64 + mt*16 + r0;
#pragma unroll
        for (int nt = 0; nt < 4; nt++) {
            const int col = n0 + wn*32 + nt*8 + c0;
            float b0v = 0.f, b1v = 0.f;
            if (hasb) { b0v = bias[col - bias_lo]; b1v = bias[col + 1 - bias_lo]; }
            float v00 = acc[mt][nt][0] + b0v;
            float v01 = acc[mt][nt][1] + b1v;
            float v10 = acc[mt][nt][2] + b0v;
            float v11 = acc[mt][nt][3] + b1v;
            if (act) {
                v00 = 1.f / (1.f + __expf(-v00));
                v01 = 1.f / (1.f + __expf(-v01));
                v10 = 1.f / (1.f + __expf(-v10));
                v11 = 1.f / (1.f + __expf(-v11));
            }
            float2 p0; p0.x = v00; p0.y = v01;
            float2 p1; p1.x = v10; p1.y = v11;
            *(float2*)(C + (size_t)row * Nt + col)       = p0;
            *(float2*)(C + (size_t)(row + 8) * Nt + col) = p1;
        }
    }
}

// ------ fused depthwise causal conv (K=4)+silu AND beta projection ----------
// blocks [0, 16384): conv, 4 timesteps/thread; [16384, 24576): beta.
#define CONVBLK 16384

__global__ __launch_bounds__(256) void conv_beta(
    const float* __restrict__ P, const float* __restrict__ x,
    const float* __restrict__ qw, const float* __restrict__ qb,
    const float* __restrict__ kw, const float* __restrict__ kb2,
    const float* __restrict__ vw, const float* __restrict__ vb2,
    const float* __restrict__ Wb, const float* __restrict__ bb,
    float* __restrict__ Qc, float* __restrict__ Kc, float* __restrict__ Vc,
    float* __restrict__ Bt)
{
    if (blockIdx.x >= CONVBLK) {
        const int m = blockIdx.x - CONVBLK;
        const int w = threadIdx.x >> 5;
        const int lane = threadIdx.x & 31;
        const float* xr = x  + (size_t)m * HIDD;
        const float* wr = Wb + (size_t)w * HIDD;
        float s = 0.f;
#pragma unroll
        for (int k = lane * 4; k < HIDD; k += 128) {
            float4 xv = *(const float4*)(xr + k);
            float4 wv = *(const float4*)(wr + k);
            s += xv.x*wv.x + xv.y*wv.y + xv.z*wv.z + xv.w*wv.w;
        }
#pragma unroll
        for (int o = 16; o; o >>= 1) s += __shfl_xor_sync(0xffffffffu, s, o);
        if (lane == 0) Bt[m*8 + w] = 1.f / (1.f + __expf(-(s + bb[w])));
        return;
    }

    const int idx = blockIdx.x * 256 + threadIdx.x;
    const int ch = idx & 2047;
    const int g  = idx >> 11;
    const int m0 = g * 4;
    const int t0 = m0 & (TSEQ - 1);

    const float* wc; float bias0, scale; float* outp; int outC, oc;
    if (ch < 512)       { wc = qw + ch*4;        bias0 = qb[ch];        scale = 1.f;
                          outp = Qc; outC = 512;  oc = ch; }
    else if (ch < 1024) { const int c2 = ch-512; wc = kw + c2*4; bias0 = kb2[c2];
                          scale = 0.125f; outp = Kc; outC = 512; oc = c2; }
    else                { const int c2 = ch-1024; wc = vw + c2*4; bias0 = vb2[c2];
                          scale = 1.f; outp = Vc; outC = 1024; oc = c2; }

    const float* in = P + ch;
    float xv[7];
#pragma unroll
    for (int j = 0; j < 7; j++)
        xv[j] = (t0 - 3 + j >= 0) ? in[(size_t)(m0 - 3 + j) * 4096] : 0.f;

    const float w0 = wc[0], w1 = wc[1], w2 = wc[2], w3 = wc[3];
#pragma unroll
    for (int i = 0; i < 4; i++) {
        float a = bias0;
        a = fmaf(w0, xv[i],   a);
        a = fmaf(w1, xv[i+1], a);
        a = fmaf(w2, xv[i+2], a);
        a = fmaf(w3, xv[i+3], a);
        const float s = a * (1.f / (1.f + __expf(-a)));
        outp[(size_t)(m0 + i) * outC + oc] = s * scale;
    }
}

// ---------------- gated delta-rule recurrence (R11, proven 245us) -----------
#define DCH 16

__global__ __launch_bounds__(64) void delta_recurrence(
    const float* __restrict__ Qc, const float* __restrict__ Kc,
    const float* __restrict__ Vc, const float* __restrict__ P,
    const float* __restrict__ Bt, float* __restrict__ O)
{
    const int bh = blockIdx.x;
    const int b = bh >> 3, h = bh & 7;
    const int tid = threadIdx.x;
    const int q_  = tid & 3;
    const int col = tid >> 2;

    __shared__ __align__(16) float sk[2][DCH][72];
    __shared__ __align__(16) float sq[2][DCH][72];
    __shared__ __align__(16) float sv[2][DCH][16];
    __shared__ __align__(16) float sa[2][DCH][16];
    __shared__ __align__(16) float sbe[2][DCH];

    const uint32_t skb = smem_u32(sk);
    const uint32_t sqb = smem_u32(sq);
    const uint32_t svb = smem_u32(sv);
    const uint32_t sab = smem_u32(sa);
    const uint32_t sbb = smem_u32(sbe);

    float S[16];
#pragma unroll
    for (int i = 0; i < 16; i++) S[i] = 0.f;

    const float* kb  = Kc + (size_t)b * TSEQ * 512  + h * 64;
    const float* qb  = Qc + (size_t)b * TSEQ * 512  + h * 64;
    const float* vb  = Vc + (size_t)b * TSEQ * 1024 + h * 128 + blockIdx.y * 16;
    const float* ab  = P  + (size_t)b * TSEQ * 4096 + 2048 + h * 128 + blockIdx.y * 16;
    const float* bbp = Bt + (size_t)b * TSEQ * 8    + h;
    float*       ob  = O  + (size_t)b * TSEQ * 1024 + h * 128 + blockIdx.y * 16 + col;

#define DSTAGE(buf, t0) do {                                                    \
    _Pragma("unroll")                                                           \
    for (int i = 0; i < 4; i++) {                                               \
        const int idx = i * 64 + tid;                                           \
        const int row = idx >> 4, seg = idx & 15;                               \
        CPA16(skb + (uint32_t)(buf) * (DCH*72*4) + row * 288u + seg * 16u,      \
              kb + (size_t)((t0) + row) * 512 + seg * 4);                       \
        CPA16(sqb + (uint32_t)(buf) * (DCH*72*4) + row * 288u + seg * 16u,      \
              qb + (size_t)((t0) + row) * 512 + seg * 4);                       \
    }                                                                           \
    {                                                                           \
        const int row = tid >> 2, seg = tid & 3;                                \
        CPA16(svb + (uint32_t)(buf) * (DCH*16*4) + row * 64u + seg * 16u,       \
              vb + (size_t)((t0) + row) * 1024 + seg * 4);                      \
        CPA16(sab + (uint32_t)(buf) * (DCH*16*4) + row * 64u + seg * 16u,       \
              ab + (size_t)((t0) + row) * 4096 + seg * 4);                      \
    }                                                                           \
    if (tid < DCH)                                                              \
        CPA4(sbb + (uint32_t)(buf) * (DCH*4) + tid * 4u,                        \
             bbp + (size_t)((t0) + tid) * 8);                                   \
    asm volatile("cp.async.commit_group;" ::: "memory");                        \
} while (0)

    DSTAGE(0, 0);

    const int NCHUNK = TSEQ / DCH;
    for (int c = 0; c < NCHUNK; c++) {
        if (c + 1 < NCHUNK) {
            DSTAGE((c + 1) & 1, (c + 1) * DCH);
            asm volatile("cp.async.wait_group 1;" ::: "memory");
        } else {
            asm volatile("cp.async.wait_group 0;" ::: "memory");
        }
        __syncthreads();
        const int buf = c & 1;

#pragma unroll 4
        for (int t = 0; t < DCH; t++) {
            const float2* k2 = (const float2*)&sk[buf][t][0];
            const float2* q2 = (const float2*)&sq[buf][t][0];
            const float be_c = sbe[buf][t];
            const float v_c  = sv[buf][t][col];
            const float a_c  = sa[buf][t][col];

            float kr[16];
#pragma unroll
            for (int jj = 0; jj < 8; jj++) {
                const float2 kv = k2[4*jj + q_];
                kr[2*jj]   = kv.x;
                kr[2*jj+1] = kv.y;
            }
            float d0 = 0.f, d1 = 0.f, d2 = 0.f, d3 = 0.f;
#pragma unroll
            for (int jj = 0; jj < 8; jj += 2) {
                d0 = fmaf(kr[2*jj],   S[2*jj],   d0);
                d1 = fmaf(kr[2*jj+1], S[2*jj+1], d1);
                d2 = fmaf(kr[2*jj+2], S[2*jj+2], d2);
                d3 = fmaf(kr[2*jj+3], S[2*jj+3], d3);
            }
            float rd = (d0 + d1) + (d2 + d3);
            rd += __shfl_xor_sync(0xffffffffu, rd, 1);
            rd += __shfl_xor_sync(0xffffffffu, rd, 2);
            const float ncc = be_c * (v_c - rd);

            float o0 = 0.f, o1 = 0.f;
#pragma unroll
            for (int jj = 0; jj < 8; jj++) {
                const float2 qv = q2[4*jj + q_];
                S[2*jj]   = fmaf(a_c, S[2*jj],   ncc * kr[2*jj]);
                S[2*jj+1] = fmaf(a_c, S[2*jj+1], ncc * kr[2*jj+1]);
                o0 = fmaf(qv.x, S[2*jj],   o0);
                o1 = fmaf(qv.y, S[2*jj+1], o1);
            }
            float oo = o0 + o1;
            oo += __shfl_xor_sync(0xffffffffu, oo, 1);
            oo += __shfl_xor_sync(0xffffffffu, oo, 2);
            if (q_ == 0) ob[(size_t)(c * DCH + t) * 1024] = oo;
        }
        __syncthreads();
    }
}

// -------- LayerNorm over DV + sigmoid-gate multiply + fp16 convert ----------
__global__ __launch_bounds__(256) void ln_gate_fp16(
    const float* __restrict__ O, const float* __restrict__ P,
    const float* __restrict__ lnw, const float* __restrict__ lnb,
    __half* __restrict__ hi)
{
    const int g = blockIdx.x * 8 + (threadIdx.x >> 5);
    const int lane = threadIdx.x & 31;
    const int m = g >> 3, h = g & 7;
    const float* row  = O + (size_t)m * 1024 + h * 128;
    const float* grow = P + (size_t)m * 4096 + 3072 + h * 128;

    float xs[4];
    float sum = 0.f;
#pragma unroll
    for (int i = 0; i < 4; i++) { xs[i] = row[lane + 32*i]; sum += xs[i]; }
#pragma unroll
    for (int o = 16; o; o >>= 1) sum += __shfl_xor_sync(0xffffffffu, sum, o);
    const float mu = sum * (1.f / 128.f);

    float vs = 0.f;
#pragma unroll
    for (int i = 0; i < 4; i++) { const float d = xs[i] - mu; vs = fmaf(d, d, vs); }
#pragma unroll
    for (int o = 16; o; o >>= 1) vs += __shfl_xor_sync(0xffffffffu, vs, o);
    const float rstd = rsqrtf(vs * (1.f / 128.f) + 1e-5f);

#pragma unroll
    for (int i = 0; i < 4; i++) {
        const int c = lane + 32*i;
        const float val = ((xs[i] - mu) * rstd * lnw[c] + lnb[c]) * grow[c];
        hi[(size_t)m * 1024 + h * 128 + c] = __float2half_rn(val);
    }
}

// ---------------- launch ----------------------------------------------------
extern "C" void kernel_launch(void* const* d_in, const int* in_sizes, int n_in,
                              void* d_out, int out_size)
{
    const float* x   = (const float*)d_in[0];
    const float* Wq  = (const float*)d_in[1];
    const float* Wk  = (const float*)d_in[2];
    const float* Wv  = (const float*)d_in[3];
    const float* Wa  = (const float*)d_in[4];
    const float* ba  = (const float*)d_in[5];
    const float* Wb  = (const float*)d_in[6];
    const float* bbv = (const float*)d_in[7];
    const float* Wg  = (const float*)d_in[8];
    const float* Wo  = (const float*)d_in[9];
    const float* qcw = (const float*)d_in[10];
    const float* qcb = (const float*)d_in[11];
    const float* kcw = (const float*)d_in[12];
    const float* kcb = (const float*)d_in[13];
    const float* vcw = (const float*)d_in[14];
    const float* vcb = (const float*)d_in[15];
    const float* lnw = (const float*)d_in[16];
    const float* lnb = (const float*)d_in[17];
    float* outp = (float*)d_out;

    float *P, *Qc, *Kc, *Vc, *Bt, *O;
    __half *Xh, *Oh, *Wh;
    cudaGetSymbolAddress((void**)&P,  g_P);
    cudaGetSymbolAddress((void**)&Qc, g_Qc);
    cudaGetSymbolAddress((void**)&Kc, g_Kc);
    cudaGetSymbolAddress((void**)&Vc, g_Vc);
    cudaGetSymbolAddress((void**)&Bt, g_Bt);
    cudaGetSymbolAddress((void**)&O,  g_O);
    cudaGetSymbolAddress((void**)&Xh, g_Xh);
    cudaGetSymbolAddress((void**)&Oh, g_Oh);
    cudaGetSymbolAddress((void**)&Wh, g_Wh);

    cudaFuncSetAttribute(gemm_hmma, cudaFuncAttributeMaxDynamicSharedMemorySize, GSMEM);

    // 0: prep (x + all weights -> fp16)
    prep_fp16<<<(XF4 + WF4 + 255)/256, 256>>>(
        x, Wq, Wk, Wv, Wa, Wg, Wo, Xh, Wh);

    // 1: ONE fused projection GEMM (Q|K|V|A|G), N=4096, BK=64
    gemm_hmma<<<dim3(32, 64), 256, GSMEM>>>(
        Xh, Wh, ba, P, 4096,
        /*bias_lo=*/2048, /*bias_hi=*/3072, /*act_lo=*/2048);

    // 2: conv+silu (Q,K,V) fused with beta projection (R11 form)
    conv_beta<<<CONVBLK + MROWS, 256>>>(
        P, x, qcw, qcb, kcw, kcb, vcw, vcb, Wb, bbv, Qc, Kc, Vc, Bt);

    // 3: sequential gated delta-rule scan (R11 proven config)
    delta_recurrence<<<dim3(NB*NH, 8), 64>>>(Qc, Kc, Vc, P, Bt, O);

    // 4: LN + gate + fp16 convert; 5: output projection
    ln_gate_fp16<<<MROWS, 256>>>(O, P, lnw, lnb, Oh);
    gemm_hmma<<<dim3(8, 64), 256, GSMEM>>>(
        Oh, Wh + WOFF_O, nullptr, outp, 1024,
        /*bias_lo=*/0, /*bias_hi=*/0, /*act_lo=*/1 << 30);
}